// round 2
// baseline (speedup 1.0000x reference)
#include <cuda_runtime.h>
#include <cuda_bf16.h>
#include <cstdint>

// ============================================================================
// y[b,s,f] = sum_o w[o] * (x[b,s,:] . W[o,f,:] + b[o,f])
// Collapsed (exact, linearity): y = x @ W_eff^T + b_eff
//   W_eff[f,d] = sum_o w_o W[o,f,d],  b_eff[f] = sum_o w_o b[o,f]
// x: [131072, 128] fp32.  GEMM via warp-level mma.sync bf16 (baseline PTX,
// no 'a'-features — harness ptxas targets sm_103, tcgen05 unavailable).
// Precision: 3-term bf16 split  y ~= xhi*Whi + xhi*Wlo + xlo*Whi  (fp32 acc).
// ============================================================================

static constexpr int D       = 128;
static constexpr int TILE_M  = 64;
static constexpr int N_ROWS  = 16 * 8192;            // 131072
static constexpr int N_TILES = N_ROWS / TILE_M;      // 2048

// SMEM byte layout. bf16 tiles use pitch 272 B (136 bf16) so that the 8 row
// addresses of each ldmatrix 8x8 matrix land 16 B apart mod 128 -> conflict-free.
static constexpr int PITCH   = 272;
static constexpr int SM_BIAS = 0;                    // 512 B
static constexpr int SM_WHI  = 512;                  // 128*272 = 34816 B
static constexpr int SM_WLO  = SM_WHI + 128 * PITCH;
static constexpr int SM_AHI  = SM_WLO + 128 * PITCH; // 64*272 = 17408 B
static constexpr int SM_ALO  = SM_AHI + TILE_M * PITCH;
static constexpr int SM_TOTAL = SM_ALO + TILE_M * PITCH;   // 104960 B

// W_eff split to bf16 hi/lo, plain [f][d] row-major (staged to SMEM per CTA).
__device__ __nv_bfloat16 g_Whi[D * D];
__device__ __nv_bfloat16 g_Wlo[D * D];
__device__ float g_beff[D];

// ---------------- PTX helpers (baseline ISA only) ---------------------------

__device__ __forceinline__ uint32_t smem_to_u32(const void* p) {
    uint32_t a;
    asm("{ .reg .u64 t; cvta.to.shared.u64 t, %1; cvt.u32.u64 %0, t; }"
        : "=r"(a) : "l"(p));
    return a;
}

__device__ __forceinline__ void ldmatrix_x4(uint32_t& r0, uint32_t& r1,
                                            uint32_t& r2, uint32_t& r3,
                                            uint32_t addr) {
    asm volatile("ldmatrix.sync.aligned.m8n8.x4.shared.b16 {%0,%1,%2,%3}, [%4];"
                 : "=r"(r0), "=r"(r1), "=r"(r2), "=r"(r3) : "r"(addr));
}

__device__ __forceinline__ void ldmatrix_x2(uint32_t& r0, uint32_t& r1,
                                            uint32_t addr) {
    asm volatile("ldmatrix.sync.aligned.m8n8.x2.shared.b16 {%0,%1}, [%2];"
                 : "=r"(r0), "=r"(r1) : "r"(addr));
}

__device__ __forceinline__ void mma_bf16(float* c, const uint32_t* a,
                                         const uint32_t* b) {
    asm volatile(
        "mma.sync.aligned.m16n8k16.row.col.f32.bf16.bf16.f32 "
        "{%0,%1,%2,%3}, {%4,%5,%6,%7}, {%8,%9}, {%0,%1,%2,%3};"
        : "+f"(c[0]), "+f"(c[1]), "+f"(c[2]), "+f"(c[3])
        : "r"(a[0]), "r"(a[1]), "r"(a[2]), "r"(a[3]), "r"(b[0]), "r"(b[1]));
}

// ============================================================================
// Kernel 1: combine weights -> W_eff (bf16 hi/lo) and b_eff
// ============================================================================
__global__ void combine_kernel(const float* __restrict__ W,
                               const float* __restrict__ b,
                               const float* __restrict__ wsel) {
    const float w0 = wsel[0], w1 = wsel[1], w2 = wsel[2], w3 = wsel[3];
    int idx = blockIdx.x * 256 + threadIdx.x;          // 64 blocks * 256
    if (idx < D * D) {
        float v = w0 * W[idx] + w1 * W[16384 + idx]
                + w2 * W[32768 + idx] + w3 * W[49152 + idx];
        __nv_bfloat16 hi = __float2bfloat16(v);
        __nv_bfloat16 lo = __float2bfloat16(v - __bfloat162float(hi));
        g_Whi[idx] = hi;
        g_Wlo[idx] = lo;
    }
    if (blockIdx.x == 0 && threadIdx.x < D) {
        int f = threadIdx.x;
        g_beff[f] = w0 * b[f] + w1 * b[128 + f] + w2 * b[256 + f] + w3 * b[384 + f];
    }
}

// ============================================================================
// Kernel 2: per-CTA 64x128 output tile.
// 4 warps; warp w owns rows [w*16, w*16+16).  Accumulate all three split
// products into one fp32 accumulator set (they sum into y anyway).
// ============================================================================
__global__ void __launch_bounds__(128, 2)
gemm_kernel(const float* __restrict__ x, float* __restrict__ y) {
    extern __shared__ char smem[];
    const uint32_t sb  = smem_to_u32(smem);
    const int tid  = threadIdx.x;
    const int w    = tid >> 5;
    const int l    = tid & 31;

    // ---- stage W hi/lo (pitch 272) + bias ----
    {
        const uint4* whi = (const uint4*)g_Whi;
        const uint4* wlo = (const uint4*)g_Wlo;
#pragma unroll
        for (int i = tid; i < 2048; i += 128) {      // 128 rows * 16 chunks
            const int r = i >> 4, c = i & 15;
            const int off = r * PITCH + c * 16;
            *(uint4*)(smem + SM_WHI + off) = whi[i];
            *(uint4*)(smem + SM_WLO + off) = wlo[i];
        }
        ((float*)(smem + SM_BIAS))[tid] = g_beff[tid];
    }

    // ---- load x tile (64x128 fp32), split to bf16 hi/lo, store to SMEM ----
    const size_t row0 = (size_t)blockIdx.x * TILE_M;
    const float4* xg = (const float4*)(x + row0 * D);
#pragma unroll
    for (int it = 0; it < 8; it++) {                 // 1024 items / 128 thr
        const int i  = tid + it * 128;
        const int r  = i >> 4;                       // row 0..63
        const int c8 = i & 15;                       // 8-float chunk
        float4 v0 = xg[r * 32 + c8 * 2];
        float4 v1 = xg[r * 32 + c8 * 2 + 1];
        float vals[8] = {v0.x, v0.y, v0.z, v0.w, v1.x, v1.y, v1.z, v1.w};
        uint32_t hip[4], lop[4];
#pragma unroll
        for (int j = 0; j < 4; j++) {
            __nv_bfloat16 h0 = __float2bfloat16(vals[2 * j]);
            __nv_bfloat16 h1 = __float2bfloat16(vals[2 * j + 1]);
            __nv_bfloat16 l0 = __float2bfloat16(vals[2 * j]     - __bfloat162float(h0));
            __nv_bfloat16 l1 = __float2bfloat16(vals[2 * j + 1] - __bfloat162float(h1));
            hip[j] = (uint32_t)__bfloat16_as_ushort(h0) |
                     ((uint32_t)__bfloat16_as_ushort(h1) << 16);
            lop[j] = (uint32_t)__bfloat16_as_ushort(l0) |
                     ((uint32_t)__bfloat16_as_ushort(l1) << 16);
        }
        const int off = r * PITCH + c8 * 16;
        *(uint4*)(smem + SM_AHI + off) = make_uint4(hip[0], hip[1], hip[2], hip[3]);
        *(uint4*)(smem + SM_ALO + off) = make_uint4(lop[0], lop[1], lop[2], lop[3]);
    }

    __syncthreads();

    // ---- main loop: 8 k-steps x 16 n-tiles x 3 split products ----
    float acc[16][4];
#pragma unroll
    for (int nt = 0; nt < 16; nt++)
#pragma unroll
        for (int j = 0; j < 4; j++) acc[nt][j] = 0.0f;

    // ldmatrix address offsets (per-lane, constant across k-steps)
    // A (16x16, row-major): lane -> row (l&15), col-half (l>>4)*8
    const uint32_t aoff = (uint32_t)((w * 16 + (l & 15)) * PITCH + ((l >> 4) & 1) * 16);
    // B (8 n-rows x 16 k): lanes 0-7 -> k-lo half, 8-15 -> k-hi half
    const uint32_t boff = (uint32_t)(((l & 7)) * PITCH + (((l >> 3) & 1) & 1) * 16);

    const uint32_t sAhi = sb + SM_AHI, sAlo = sb + SM_ALO;
    const uint32_t sWhi = sb + SM_WHI, sWlo = sb + SM_WLO;

#pragma unroll
    for (int ks = 0; ks < 8; ks++) {
        const uint32_t kb = (uint32_t)ks * 32;       // 16 bf16 = 32 bytes
        uint32_t ahi[4], alo[4];
        ldmatrix_x4(ahi[0], ahi[1], ahi[2], ahi[3], sAhi + aoff + kb);
        ldmatrix_x4(alo[0], alo[1], alo[2], alo[3], sAlo + aoff + kb);
#pragma unroll
        for (int nt = 0; nt < 16; nt++) {
            const uint32_t nb = (uint32_t)nt * (8 * PITCH);
            uint32_t bhi[2], blo[2];
            ldmatrix_x2(bhi[0], bhi[1], sWhi + boff + nb + kb);
            ldmatrix_x2(blo[0], blo[1], sWlo + boff + nb + kb);
            mma_bf16(acc[nt], ahi, bhi);
            mma_bf16(acc[nt], ahi, blo);
            mma_bf16(acc[nt], alo, bhi);
        }
    }

    // ---- epilogue: add bias, store fp32 ----
    const float* bsm = (const float*)(smem + SM_BIAS);
    const int rlo = (int)row0 + w * 16 + (l >> 2);   // rows l/4 and l/4+8
    const int cpair = (l & 3) * 2;
#pragma unroll
    for (int nt = 0; nt < 16; nt++) {
        const int col = nt * 8 + cpair;
        const float bx = bsm[col], by = bsm[col + 1];
        float2 v0 = make_float2(acc[nt][0] + bx, acc[nt][1] + by);
        float2 v1 = make_float2(acc[nt][2] + bx, acc[nt][3] + by);
        *(float2*)(y + (size_t)rlo * D + col)       = v0;
        *(float2*)(y + (size_t)(rlo + 8) * D + col) = v1;
    }
}

// ============================================================================

extern "C" void kernel_launch(void* const* d_in, const int* in_sizes, int n_in,
                              void* d_out, int out_size) {
    const float* x    = (const float*)d_in[0];  // [16, 8192, 128]
    const float* W    = (const float*)d_in[1];  // [4, 128, 128]
    const float* b    = (const float*)d_in[2];  // [4, 128]
    const float* wsel = (const float*)d_in[3];  // [4]
    float* y = (float*)d_out;                   // [16, 8192, 128]

    combine_kernel<<<64, 256>>>(W, b, wsel);

    static bool attr_set = false;
    if (!attr_set) {
        cudaFuncSetAttribute(gemm_kernel,
                             cudaFuncAttributeMaxDynamicSharedMemorySize, SM_TOTAL);
        attr_set = true;
    }
    gemm_kernel<<<N_TILES, 128, SM_TOTAL>>>(x, y);
}

// round 3
// speedup vs baseline: 1.3451x; 1.3451x over previous
#include <cuda_runtime.h>
#include <cuda_bf16.h>
#include <cstdint>

// ============================================================================
// y = x @ W_eff^T + b_eff   (exact collapse of the one-hot op mixture)
// x: [131072, 128] fp32.  Warp-level mma.sync bf16, 3-term split
// (xhi*Whi + xhi*Wlo + xlo*Whi), fp32 accum.
// R3 change: warp tile 16x128 -> 32x64 (2Mx2N warp grid) + ldmatrix.x4 for B
// (pairs of n-tiles) => ~3x fewer ldmatrix issues, ~1.5x less SMEM traffic.
// ============================================================================

static constexpr int D       = 128;
static constexpr int TILE_M  = 64;
static constexpr int N_ROWS  = 16 * 8192;            // 131072
static constexpr int N_TILES = N_ROWS / TILE_M;      // 2048

// bf16 tiles use pitch 272 B so ldmatrix row addresses spread across banks.
static constexpr int PITCH   = 272;
static constexpr int SM_BIAS = 0;                    // 512 B
static constexpr int SM_WHI  = 512;
static constexpr int SM_WLO  = SM_WHI + 128 * PITCH;
static constexpr int SM_AHI  = SM_WLO + 128 * PITCH;
static constexpr int SM_ALO  = SM_AHI + TILE_M * PITCH;
static constexpr int SM_TOTAL = SM_ALO + TILE_M * PITCH;   // 104960 B

__device__ __nv_bfloat16 g_Whi[D * D];
__device__ __nv_bfloat16 g_Wlo[D * D];
__device__ float g_beff[D];

// ---------------- PTX helpers (baseline ISA only) ---------------------------

__device__ __forceinline__ uint32_t smem_to_u32(const void* p) {
    uint32_t a;
    asm("{ .reg .u64 t; cvta.to.shared.u64 t, %1; cvt.u32.u64 %0, t; }"
        : "=r"(a) : "l"(p));
    return a;
}

__device__ __forceinline__ void ldmatrix_x4(uint32_t& r0, uint32_t& r1,
                                            uint32_t& r2, uint32_t& r3,
                                            uint32_t addr) {
    asm volatile("ldmatrix.sync.aligned.m8n8.x4.shared.b16 {%0,%1,%2,%3}, [%4];"
                 : "=r"(r0), "=r"(r1), "=r"(r2), "=r"(r3) : "r"(addr));
}

__device__ __forceinline__ void mma_bf16(float* c, const uint32_t* a,
                                         const uint32_t* b) {
    asm volatile(
        "mma.sync.aligned.m16n8k16.row.col.f32.bf16.bf16.f32 "
        "{%0,%1,%2,%3}, {%4,%5,%6,%7}, {%8,%9}, {%0,%1,%2,%3};"
        : "+f"(c[0]), "+f"(c[1]), "+f"(c[2]), "+f"(c[3])
        : "r"(a[0]), "r"(a[1]), "r"(a[2]), "r"(a[3]), "r"(b[0]), "r"(b[1]));
}

// ============================================================================
// Kernel 1: combine weights -> W_eff (bf16 hi/lo) and b_eff
// ============================================================================
__global__ void combine_kernel(const float* __restrict__ W,
                               const float* __restrict__ b,
                               const float* __restrict__ wsel) {
    const float w0 = wsel[0], w1 = wsel[1], w2 = wsel[2], w3 = wsel[3];
    int idx = blockIdx.x * 256 + threadIdx.x;          // 64 blocks * 256
    if (idx < D * D) {
        float v = w0 * W[idx] + w1 * W[16384 + idx]
                + w2 * W[32768 + idx] + w3 * W[49152 + idx];
        __nv_bfloat16 hi = __float2bfloat16(v);
        __nv_bfloat16 lo = __float2bfloat16(v - __bfloat162float(hi));
        g_Whi[idx] = hi;
        g_Wlo[idx] = lo;
    }
    if (blockIdx.x == 0 && threadIdx.x < D) {
        int f = threadIdx.x;
        g_beff[f] = w0 * b[f] + w1 * b[128 + f] + w2 * b[256 + f] + w3 * b[384 + f];
    }
}

// ============================================================================
// Kernel 2: per-CTA 64x128 tile; 4 warps in 2Mx2N grid, each warp 32x64.
// ============================================================================
__global__ void __launch_bounds__(128, 2)
gemm_kernel(const float* __restrict__ x, float* __restrict__ y) {
    extern __shared__ char smem[];
    const uint32_t sb  = smem_to_u32(smem);
    const int tid  = threadIdx.x;
    const int w    = tid >> 5;
    const int l    = tid & 31;
    const int mw   = w & 1;          // M half  (rows mw*32 .. +31)
    const int nw   = w >> 1;         // N half  (cols nw*64 .. +63)

    // ---- stage W hi/lo (pitch 272) + bias ----
    {
        const uint4* whi = (const uint4*)g_Whi;
        const uint4* wlo = (const uint4*)g_Wlo;
#pragma unroll
        for (int i = tid; i < 2048; i += 128) {      // 128 rows * 16 chunks
            const int r = i >> 4, c = i & 15;
            const int off = r * PITCH + c * 16;
            *(uint4*)(smem + SM_WHI + off) = whi[i];
            *(uint4*)(smem + SM_WLO + off) = wlo[i];
        }
        ((float*)(smem + SM_BIAS))[tid] = g_beff[tid];
    }

    // ---- load x tile (64x128 fp32), split to bf16 hi/lo, store to SMEM ----
    const size_t row0 = (size_t)blockIdx.x * TILE_M;
    const float4* xg = (const float4*)(x + row0 * D);
#pragma unroll
    for (int it = 0; it < 8; it++) {                 // 1024 chunks / 128 thr
        const int i  = tid + it * 128;
        const int r  = i >> 4;                       // row 0..63
        const int c8 = i & 15;                       // 8-float chunk
        float4 v0 = xg[r * 32 + c8 * 2];
        float4 v1 = xg[r * 32 + c8 * 2 + 1];
        float vals[8] = {v0.x, v0.y, v0.z, v0.w, v1.x, v1.y, v1.z, v1.w};
        uint32_t hip[4], lop[4];
#pragma unroll
        for (int j = 0; j < 4; j++) {
            __nv_bfloat16 h0 = __float2bfloat16(vals[2 * j]);
            __nv_bfloat16 h1 = __float2bfloat16(vals[2 * j + 1]);
            __nv_bfloat16 l0 = __float2bfloat16(vals[2 * j]     - __bfloat162float(h0));
            __nv_bfloat16 l1 = __float2bfloat16(vals[2 * j + 1] - __bfloat162float(h1));
            hip[j] = (uint32_t)__bfloat16_as_ushort(h0) |
                     ((uint32_t)__bfloat16_as_ushort(h1) << 16);
            lop[j] = (uint32_t)__bfloat16_as_ushort(l0) |
                     ((uint32_t)__bfloat16_as_ushort(l1) << 16);
        }
        const int off = r * PITCH + c8 * 16;
        *(uint4*)(smem + SM_AHI + off) = make_uint4(hip[0], hip[1], hip[2], hip[3]);
        *(uint4*)(smem + SM_ALO + off) = make_uint4(lop[0], lop[1], lop[2], lop[3]);
    }

    __syncthreads();

    // ---- main loop ----
    // acc[mt][nt][4]: mt in {0,1} (16-row subtiles), nt in 0..7 (8-col tiles)
    float acc[2][8][4];
#pragma unroll
    for (int mt = 0; mt < 2; mt++)
#pragma unroll
        for (int nt = 0; nt < 8; nt++)
#pragma unroll
            for (int j = 0; j < 4; j++) acc[mt][nt][j] = 0.0f;

    // A x4 (16x16 tile): lane addr = row (l&15) within tile, k-half (l>>4)
    const uint32_t aoff0 = (uint32_t)((mw * 32 +      (l & 15)) * PITCH + ((l >> 4) & 1) * 16);
    const uint32_t aoff1 = (uint32_t)((mw * 32 + 16 + (l & 15)) * PITCH + ((l >> 4) & 1) * 16);
    // B x4 (two n-tiles x k16): lanes 0-7 nt rows k-lo, 8-15 nt rows k-hi,
    //                           16-23 nt+1 rows k-lo, 24-31 nt+1 rows k-hi
    const uint32_t boff = (uint32_t)((((l >> 4) & 1) * 8 + (l & 7)) * PITCH
                                     + ((l >> 3) & 1) * 16);

    const uint32_t sAhi = sb + SM_AHI, sAlo = sb + SM_ALO;
    const uint32_t sWhi = sb + SM_WHI, sWlo = sb + SM_WLO;

#pragma unroll
    for (int ks = 0; ks < 8; ks++) {
        const uint32_t kb = (uint32_t)ks * 32;       // 16 bf16 = 32 bytes
        uint32_t ahi[2][4], alo[2][4];
        ldmatrix_x4(ahi[0][0], ahi[0][1], ahi[0][2], ahi[0][3], sAhi + aoff0 + kb);
        ldmatrix_x4(ahi[1][0], ahi[1][1], ahi[1][2], ahi[1][3], sAhi + aoff1 + kb);
        ldmatrix_x4(alo[0][0], alo[0][1], alo[0][2], alo[0][3], sAlo + aoff0 + kb);
        ldmatrix_x4(alo[1][0], alo[1][1], alo[1][2], alo[1][3], sAlo + aoff1 + kb);

#pragma unroll
        for (int np = 0; np < 4; np++) {             // n-tile pairs
            const uint32_t nb = (uint32_t)(nw * 64 + np * 16) * PITCH;  // 2 tiles = 16 rows
            uint32_t bhi[4], blo[4];
            ldmatrix_x4(bhi[0], bhi[1], bhi[2], bhi[3], sWhi + boff + nb + kb);
            ldmatrix_x4(blo[0], blo[1], blo[2], blo[3], sWlo + boff + nb + kb);
#pragma unroll
            for (int j = 0; j < 2; j++) {            // the two n-tiles in the pair
                const int nt = np * 2 + j;
#pragma unroll
                for (int mt = 0; mt < 2; mt++) {
                    mma_bf16(acc[mt][nt], ahi[mt], &bhi[2 * j]);
                    mma_bf16(acc[mt][nt], ahi[mt], &blo[2 * j]);
                    mma_bf16(acc[mt][nt], alo[mt], &bhi[2 * j]);
                }
            }
        }
    }

    // ---- epilogue: add bias, store fp32 ----
    const float* bsm = (const float*)(smem + SM_BIAS);
    const int cpair = (l & 3) * 2;
#pragma unroll
    for (int mt = 0; mt < 2; mt++) {
        const size_t rbase = row0 + mw * 32 + mt * 16 + (l >> 2);
#pragma unroll
        for (int nt = 0; nt < 8; nt++) {
            const int col = nw * 64 + nt * 8 + cpair;
            const float bx = bsm[col], by = bsm[col + 1];
            float2 v0 = make_float2(acc[mt][nt][0] + bx, acc[mt][nt][1] + by);
            float2 v1 = make_float2(acc[mt][nt][2] + bx, acc[mt][nt][3] + by);
            *(float2*)(y + rbase * D + col)       = v0;
            *(float2*)(y + (rbase + 8) * D + col) = v1;
        }
    }
}

// ============================================================================

extern "C" void kernel_launch(void* const* d_in, const int* in_sizes, int n_in,
                              void* d_out, int out_size) {
    const float* x    = (const float*)d_in[0];  // [16, 8192, 128]
    const float* W    = (const float*)d_in[1];  // [4, 128, 128]
    const float* b    = (const float*)d_in[2];  // [4, 128]
    const float* wsel = (const float*)d_in[3];  // [4]
    float* y = (float*)d_out;                   // [16, 8192, 128]

    combine_kernel<<<64, 256>>>(W, b, wsel);

    static bool attr_set = false;
    if (!attr_set) {
        cudaFuncSetAttribute(gemm_kernel,
                             cudaFuncAttributeMaxDynamicSharedMemorySize, SM_TOTAL);
        attr_set = true;
    }
    gemm_kernel<<<N_TILES, 128, SM_TOTAL>>>(x, y);
}

// round 4
// speedup vs baseline: 1.5350x; 1.1412x over previous
#include <cuda_runtime.h>
#include <cuda_bf16.h>
#include <cstdint>

// ============================================================================
// y = x @ W_eff^T + b_eff   (exact collapse of the one-hot op mixture)
// x: [131072, 128] fp32.  Warp-level mma.sync bf16, 3-term split
// (xhi*Whi + xhi*Wlo + xlo*Whi), fp32 accum.
// R4: single persistent-grid kernel (148 CTAs x 256 thr, 1 CTA/SM),
//     TILE_M=128, double-buffered A in SMEM, LDG of next tile issued before
//     the MMA phase so DRAM latency hides under tensor work. W_eff computed
//     in-prologue (combine kernel folded in; one launch total).
// ============================================================================

static constexpr int D       = 128;
static constexpr int TILE_M  = 128;
static constexpr int N_ROWS  = 16 * 8192;            // 131072
static constexpr int N_TILES = N_ROWS / TILE_M;      // 1024
static constexpr int GRID    = 148;                  // persistent, 1 CTA/SM
static constexpr int NTHR    = 256;                  // 8 warps: 4M x 2N

// bf16 tiles: pitch 272 B keeps ldmatrix row addresses conflict-free.
static constexpr int PITCH   = 272;
static constexpr int WTILE   = 128 * PITCH;          // 34816 B
static constexpr int SM_WHI  = 0;
static constexpr int SM_WLO  = SM_WHI + WTILE;
static constexpr int SM_A0HI = SM_WLO + WTILE;
static constexpr int SM_A0LO = SM_A0HI + WTILE;
static constexpr int SM_A1HI = SM_A0LO + WTILE;
static constexpr int SM_A1LO = SM_A1HI + WTILE;
static constexpr int SM_TOTAL = SM_A1LO + WTILE;     // 208896 B

// ---------------- PTX helpers (baseline ISA only) ---------------------------

__device__ __forceinline__ uint32_t smem_to_u32(const void* p) {
    uint32_t a;
    asm("{ .reg .u64 t; cvta.to.shared.u64 t, %1; cvt.u32.u64 %0, t; }"
        : "=r"(a) : "l"(p));
    return a;
}

__device__ __forceinline__ void ldmatrix_x4(uint32_t& r0, uint32_t& r1,
                                            uint32_t& r2, uint32_t& r3,
                                            uint32_t addr) {
    asm volatile("ldmatrix.sync.aligned.m8n8.x4.shared.b16 {%0,%1,%2,%3}, [%4];"
                 : "=r"(r0), "=r"(r1), "=r"(r2), "=r"(r3) : "r"(addr));
}

__device__ __forceinline__ void mma_bf16(float* c, const uint32_t* a,
                                         const uint32_t* b) {
    asm volatile(
        "mma.sync.aligned.m16n8k16.row.col.f32.bf16.bf16.f32 "
        "{%0,%1,%2,%3}, {%4,%5,%6,%7}, {%8,%9}, {%0,%1,%2,%3};"
        : "+f"(c[0]), "+f"(c[1]), "+f"(c[2]), "+f"(c[3])
        : "r"(a[0]), "r"(a[1]), "r"(a[2]), "r"(a[3]), "r"(b[0]), "r"(b[1]));
}

__device__ __forceinline__ uint32_t pack_hi(float a, float b) {
    __nv_bfloat16 h0 = __float2bfloat16(a);
    __nv_bfloat16 h1 = __float2bfloat16(b);
    return (uint32_t)__bfloat16_as_ushort(h0) |
           ((uint32_t)__bfloat16_as_ushort(h1) << 16);
}
__device__ __forceinline__ uint32_t pack_lo(float a, float b) {
    __nv_bfloat16 h0 = __float2bfloat16(a);
    __nv_bfloat16 h1 = __float2bfloat16(b);
    __nv_bfloat16 l0 = __float2bfloat16(a - __bfloat162float(h0));
    __nv_bfloat16 l1 = __float2bfloat16(b - __bfloat162float(h1));
    return (uint32_t)__bfloat16_as_ushort(l0) |
           ((uint32_t)__bfloat16_as_ushort(l1) << 16);
}

// issue the 16 LDG.128 for one 128x128 fp32 tile (per-thread share)
__device__ __forceinline__ void ldg_tile(const float4* __restrict__ xg,
                                         int tid, float4* st) {
#pragma unroll
    for (int it = 0; it < 8; it++) {
        const int i  = tid + it * NTHR;
        const int r  = i >> 4;
        const int c8 = i & 15;
        st[2 * it]     = xg[r * 32 + c8 * 2];
        st[2 * it + 1] = xg[r * 32 + c8 * 2 + 1];
    }
}

// convert staged fp32 regs -> bf16 hi/lo and store to SMEM tile buffers
__device__ __forceinline__ void cvt_sts_tile(char* smem, int hi_off, int lo_off,
                                             int tid, const float4* st) {
#pragma unroll
    for (int it = 0; it < 8; it++) {
        const int i  = tid + it * NTHR;
        const int r  = i >> 4;
        const int c8 = i & 15;
        const float4 v0 = st[2 * it];
        const float4 v1 = st[2 * it + 1];
        uint4 hip, lop;
        hip.x = pack_hi(v0.x, v0.y);  lop.x = pack_lo(v0.x, v0.y);
        hip.y = pack_hi(v0.z, v0.w);  lop.y = pack_lo(v0.z, v0.w);
        hip.z = pack_hi(v1.x, v1.y);  lop.z = pack_lo(v1.x, v1.y);
        hip.w = pack_hi(v1.z, v1.w);  lop.w = pack_lo(v1.z, v1.w);
        const int off = r * PITCH + c8 * 16;
        *(uint4*)(smem + hi_off + off) = hip;
        *(uint4*)(smem + lo_off + off) = lop;
    }
}

// ============================================================================
__global__ void __launch_bounds__(NTHR, 1)
gemm_kernel(const float* __restrict__ x,
            const float* __restrict__ W,
            const float* __restrict__ bias,
            const float* __restrict__ wsel,
            float* __restrict__ y) {
    extern __shared__ char smem[];
    const uint32_t sb  = smem_to_u32(smem);
    const int tid  = threadIdx.x;
    const int w    = tid >> 5;
    const int l    = tid & 31;
    const int mw   = w & 3;          // M quarter (rows mw*32 .. +31)
    const int nw   = w >> 2;         // N half    (cols nw*64 .. +63)

    const float w0 = wsel[0], w1 = wsel[1], w2 = wsel[2], w3 = wsel[3];

    // ---- compute W_eff (bf16 hi/lo) directly into SMEM ----
#pragma unroll
    for (int j = 0; j < 64; j++) {                   // 16384 / 256
        const int idx = tid + j * NTHR;
        const float v = w0 * W[idx] + w1 * W[16384 + idx]
                      + w2 * W[32768 + idx] + w3 * W[49152 + idx];
        __nv_bfloat16 hi = __float2bfloat16(v);
        __nv_bfloat16 lo = __float2bfloat16(v - __bfloat162float(hi));
        const int f = idx >> 7, d = idx & 127;
        const int off = f * PITCH + d * 2;
        *(__nv_bfloat16*)(smem + SM_WHI + off) = hi;
        *(__nv_bfloat16*)(smem + SM_WLO + off) = lo;
    }

    // ---- per-lane bias values (constant across tiles) ----
    const int cpair = (l & 3) * 2;
    float bx[8], by[8];
#pragma unroll
    for (int nt = 0; nt < 8; nt++) {
        const int col = nw * 64 + nt * 8 + cpair;
        bx[nt] = w0 * bias[col]     + w1 * bias[128 + col]
               + w2 * bias[256 + col] + w3 * bias[384 + col];
        by[nt] = w0 * bias[col + 1]   + w1 * bias[129 + col]
               + w2 * bias[257 + col] + w3 * bias[385 + col];
    }

    // ---- prologue: load + convert + store tile t0 into buffer 0 ----
    int t = blockIdx.x;
    {
        float4 st[16];
        ldg_tile((const float4*)(x + (size_t)t * TILE_M * D), tid, st);
        cvt_sts_tile(smem, SM_A0HI, SM_A0LO, tid, st);
    }
    __syncthreads();

    // ldmatrix per-lane offsets
    const uint32_t aoff0 = (uint32_t)((mw * 32 +      (l & 15)) * PITCH + ((l >> 4) & 1) * 16);
    const uint32_t aoff1 = aoff0 + 16u * PITCH;
    const uint32_t boff  = (uint32_t)((((l >> 4) & 1) * 8 + (l & 7)) * PITCH
                                      + ((l >> 3) & 1) * 16);
    const uint32_t sWhi = sb + SM_WHI, sWlo = sb + SM_WLO;

    int cur = 0;
    for (; t < N_TILES; t += GRID) {
        const int tn = t + GRID;
        const bool have_next = tn < N_TILES;

        // 1) issue next tile's global loads (latency hides under MMAs)
        float4 st[16];
        if (have_next)
            ldg_tile((const float4*)(x + (size_t)tn * TILE_M * D), tid, st);

        // 2) MMA phase on buffer `cur`
        const uint32_t sAhi = sb + (cur ? SM_A1HI : SM_A0HI);
        const uint32_t sAlo = sb + (cur ? SM_A1LO : SM_A0LO);

        float acc[2][8][4];
#pragma unroll
        for (int mt = 0; mt < 2; mt++)
#pragma unroll
            for (int nt = 0; nt < 8; nt++)
#pragma unroll
                for (int j = 0; j < 4; j++) acc[mt][nt][j] = 0.0f;

#pragma unroll
        for (int ks = 0; ks < 8; ks++) {
            const uint32_t kb = (uint32_t)ks * 32;
            uint32_t ahi[2][4], alo[2][4];
            ldmatrix_x4(ahi[0][0], ahi[0][1], ahi[0][2], ahi[0][3], sAhi + aoff0 + kb);
            ldmatrix_x4(ahi[1][0], ahi[1][1], ahi[1][2], ahi[1][3], sAhi + aoff1 + kb);
            ldmatrix_x4(alo[0][0], alo[0][1], alo[0][2], alo[0][3], sAlo + aoff0 + kb);
            ldmatrix_x4(alo[1][0], alo[1][1], alo[1][2], alo[1][3], sAlo + aoff1 + kb);

#pragma unroll
            for (int np = 0; np < 4; np++) {
                const uint32_t nb = (uint32_t)(nw * 64 + np * 16) * PITCH;
                uint32_t bhi[4], blo[4];
                ldmatrix_x4(bhi[0], bhi[1], bhi[2], bhi[3], sWhi + boff + nb + kb);
                ldmatrix_x4(blo[0], blo[1], blo[2], blo[3], sWlo + boff + nb + kb);
#pragma unroll
                for (int j = 0; j < 2; j++) {
                    const int nt = np * 2 + j;
#pragma unroll
                    for (int mt = 0; mt < 2; mt++) {
                        mma_bf16(acc[mt][nt], ahi[mt], &bhi[2 * j]);
                        mma_bf16(acc[mt][nt], ahi[mt], &blo[2 * j]);
                        mma_bf16(acc[mt][nt], alo[mt], &bhi[2 * j]);
                    }
                }
            }
        }

        // 3) convert + store next tile into the other buffer
        if (have_next)
            cvt_sts_tile(smem, cur ? SM_A0HI : SM_A1HI,
                               cur ? SM_A0LO : SM_A1LO, tid, st);

        // 4) epilogue: bias + STG for tile t
#pragma unroll
        for (int mt = 0; mt < 2; mt++) {
            const size_t rbase = (size_t)t * TILE_M + mw * 32 + mt * 16 + (l >> 2);
#pragma unroll
            for (int nt = 0; nt < 8; nt++) {
                const int col = nw * 64 + nt * 8 + cpair;
                float2 v0 = make_float2(acc[mt][nt][0] + bx[nt], acc[mt][nt][1] + by[nt]);
                float2 v1 = make_float2(acc[mt][nt][2] + bx[nt], acc[mt][nt][3] + by[nt]);
                *(float2*)(y + rbase * D + col)       = v0;
                *(float2*)(y + (rbase + 8) * D + col) = v1;
            }
        }

        __syncthreads();
        cur ^= 1;
    }
}

// ============================================================================

extern "C" void kernel_launch(void* const* d_in, const int* in_sizes, int n_in,
                              void* d_out, int out_size) {
    const float* x    = (const float*)d_in[0];  // [16, 8192, 128]
    const float* W    = (const float*)d_in[1];  // [4, 128, 128]
    const float* b    = (const float*)d_in[2];  // [4, 128]
    const float* wsel = (const float*)d_in[3];  // [4]
    float* y = (float*)d_out;                   // [16, 8192, 128]

    static bool attr_set = false;
    if (!attr_set) {
        cudaFuncSetAttribute(gemm_kernel,
                             cudaFuncAttributeMaxDynamicSharedMemorySize, SM_TOTAL);
        attr_set = true;
    }
    gemm_kernel<<<GRID, NTHR, SM_TOTAL>>>(x, W, b, wsel, y);
}

// round 5
// speedup vs baseline: 1.5766x; 1.0271x over previous
#include <cuda_runtime.h>
#include <cuda_bf16.h>
#include <cstdint>

// ============================================================================
// y = x @ W_eff^T + b_eff   (exact collapse of the one-hot op mixture)
// x: [131072, 128] fp32.  Warp-level mma.sync bf16, 3-term split
// (xhi*Whi + xhi*Wlo + xlo*Whi), fp32 accum.
// R5: (a) B fragments register-resident per k-step; MMAs grouped by split
//     product so same-accumulator reuse distance is 16 MMAs (kills RAW
//     stalls on the tensor pipe).  (b) next-tile convert+STS drained in two
//     halves inside the MMA loop to cut peak register pressure (no spills).
// ============================================================================

static constexpr int D       = 128;
static constexpr int TILE_M  = 128;
static constexpr int N_ROWS  = 16 * 8192;            // 131072
static constexpr int N_TILES = N_ROWS / TILE_M;      // 1024
static constexpr int GRID    = 148;                  // persistent, 1 CTA/SM
static constexpr int NTHR    = 256;                  // 8 warps: 4M x 2N

// bf16 tiles: pitch 272 B keeps ldmatrix row addresses conflict-free.
static constexpr int PITCH   = 272;
static constexpr int WTILE   = 128 * PITCH;          // 34816 B
static constexpr int SM_WHI  = 0;
static constexpr int SM_WLO  = SM_WHI + WTILE;
static constexpr int SM_A0HI = SM_WLO + WTILE;
static constexpr int SM_A0LO = SM_A0HI + WTILE;
static constexpr int SM_A1HI = SM_A0LO + WTILE;
static constexpr int SM_A1LO = SM_A1HI + WTILE;
static constexpr int SM_TOTAL = SM_A1LO + WTILE;     // 208896 B

// ---------------- PTX helpers (baseline ISA only) ---------------------------

__device__ __forceinline__ uint32_t smem_to_u32(const void* p) {
    uint32_t a;
    asm("{ .reg .u64 t; cvta.to.shared.u64 t, %1; cvt.u32.u64 %0, t; }"
        : "=r"(a) : "l"(p));
    return a;
}

__device__ __forceinline__ void ldmatrix_x4(uint32_t& r0, uint32_t& r1,
                                            uint32_t& r2, uint32_t& r3,
                                            uint32_t addr) {
    asm volatile("ldmatrix.sync.aligned.m8n8.x4.shared.b16 {%0,%1,%2,%3}, [%4];"
                 : "=r"(r0), "=r"(r1), "=r"(r2), "=r"(r3) : "r"(addr));
}

__device__ __forceinline__ void mma_bf16(float* c, const uint32_t* a,
                                         const uint32_t* b) {
    asm volatile(
        "mma.sync.aligned.m16n8k16.row.col.f32.bf16.bf16.f32 "
        "{%0,%1,%2,%3}, {%4,%5,%6,%7}, {%8,%9}, {%0,%1,%2,%3};"
        : "+f"(c[0]), "+f"(c[1]), "+f"(c[2]), "+f"(c[3])
        : "r"(a[0]), "r"(a[1]), "r"(a[2]), "r"(a[3]), "r"(b[0]), "r"(b[1]));
}

__device__ __forceinline__ uint32_t pack_hi(float a, float b) {
    __nv_bfloat16 h0 = __float2bfloat16(a);
    __nv_bfloat16 h1 = __float2bfloat16(b);
    return (uint32_t)__bfloat16_as_ushort(h0) |
           ((uint32_t)__bfloat16_as_ushort(h1) << 16);
}
__device__ __forceinline__ uint32_t pack_lo(float a, float b) {
    __nv_bfloat16 h0 = __float2bfloat16(a);
    __nv_bfloat16 h1 = __float2bfloat16(b);
    __nv_bfloat16 l0 = __float2bfloat16(a - __bfloat162float(h0));
    __nv_bfloat16 l1 = __float2bfloat16(b - __bfloat162float(h1));
    return (uint32_t)__bfloat16_as_ushort(l0) |
           ((uint32_t)__bfloat16_as_ushort(l1) << 16);
}

// issue the 16 LDG.128 for one 128x128 fp32 tile (per-thread share)
__device__ __forceinline__ void ldg_tile(const float4* __restrict__ xg,
                                         int tid, float4* st) {
#pragma unroll
    for (int it = 0; it < 8; it++) {
        const int i  = tid + it * NTHR;
        const int r  = i >> 4;
        const int c8 = i & 15;
        st[2 * it]     = xg[r * 32 + c8 * 2];
        st[2 * it + 1] = xg[r * 32 + c8 * 2 + 1];
    }
}

// convert HALF of the staged tile (it in [4h, 4h+4)) and store to SMEM
__device__ __forceinline__ void cvt_sts_half(char* smem_base, int hi_off, int lo_off,
                                             int tid, const float4* st, int h) {
#pragma unroll
    for (int it = 4 * h; it < 4 * h + 4; it++) {
        const int i  = tid + it * NTHR;
        const int r  = i >> 4;
        const int c8 = i & 15;
        const float4 v0 = st[2 * it];
        const float4 v1 = st[2 * it + 1];
        uint4 hip, lop;
        hip.x = pack_hi(v0.x, v0.y);  lop.x = pack_lo(v0.x, v0.y);
        hip.y = pack_hi(v0.z, v0.w);  lop.y = pack_lo(v0.z, v0.w);
        hip.z = pack_hi(v1.x, v1.y);  lop.z = pack_lo(v1.x, v1.y);
        hip.w = pack_hi(v1.z, v1.w);  lop.w = pack_lo(v1.z, v1.w);
        const int off = r * PITCH + c8 * 16;
        *(uint4*)(smem_base + hi_off + off) = hip;
        *(uint4*)(smem_base + lo_off + off) = lop;
    }
}

// ============================================================================
__global__ void __launch_bounds__(NTHR, 1)
gemm_kernel(const float* __restrict__ x,
            const float* __restrict__ W,
            const float* __restrict__ bias,
            const float* __restrict__ wsel,
            float* __restrict__ y) {
    extern __shared__ char smem[];
    const uint32_t sb  = smem_to_u32(smem);
    const int tid  = threadIdx.x;
    const int w    = tid >> 5;
    const int l    = tid & 31;
    const int mw   = w & 3;          // M quarter (rows mw*32 .. +31)
    const int nw   = w >> 2;         // N half    (cols nw*64 .. +63)

    const float w0 = wsel[0], w1 = wsel[1], w2 = wsel[2], w3 = wsel[3];

    // ---- compute W_eff (bf16 hi/lo) directly into SMEM ----
#pragma unroll
    for (int j = 0; j < 64; j++) {                   // 16384 / 256
        const int idx = tid + j * NTHR;
        const float v = w0 * W[idx] + w1 * W[16384 + idx]
                      + w2 * W[32768 + idx] + w3 * W[49152 + idx];
        __nv_bfloat16 hi = __float2bfloat16(v);
        __nv_bfloat16 lo = __float2bfloat16(v - __bfloat162float(hi));
        const int f = idx >> 7, d = idx & 127;
        const int off = f * PITCH + d * 2;
        *(__nv_bfloat16*)(smem + SM_WHI + off) = hi;
        *(__nv_bfloat16*)(smem + SM_WLO + off) = lo;
    }

    // ---- per-lane bias values (constant across tiles) ----
    const int cpair = (l & 3) * 2;
    float bx[8], by[8];
#pragma unroll
    for (int nt = 0; nt < 8; nt++) {
        const int col = nw * 64 + nt * 8 + cpair;
        bx[nt] = w0 * bias[col]       + w1 * bias[128 + col]
               + w2 * bias[256 + col] + w3 * bias[384 + col];
        by[nt] = w0 * bias[col + 1]   + w1 * bias[129 + col]
               + w2 * bias[257 + col] + w3 * bias[385 + col];
    }

    // ---- prologue: load + convert + store tile t0 into buffer 0 ----
    int t = blockIdx.x;
    {
        float4 st[16];
        ldg_tile((const float4*)(x + (size_t)t * TILE_M * D), tid, st);
        cvt_sts_half(smem, SM_A0HI, SM_A0LO, tid, st, 0);
        cvt_sts_half(smem, SM_A0HI, SM_A0LO, tid, st, 1);
    }
    __syncthreads();

    // ldmatrix per-lane offsets
    const uint32_t aoff0 = (uint32_t)((mw * 32 +      (l & 15)) * PITCH + ((l >> 4) & 1) * 16);
    const uint32_t aoff1 = aoff0 + 16u * PITCH;
    const uint32_t boff  = (uint32_t)((((l >> 4) & 1) * 8 + (l & 7)) * PITCH
                                      + ((l >> 3) & 1) * 16);
    const uint32_t sWhi = sb + SM_WHI, sWlo = sb + SM_WLO;

    int cur = 0;
    for (; t < N_TILES; t += GRID) {
        const int tn = t + GRID;
        const bool have_next = tn < N_TILES;

        // 1) issue next tile's global loads (latency hides under MMAs)
        float4 st[16];
        if (have_next)
            ldg_tile((const float4*)(x + (size_t)tn * TILE_M * D), tid, st);

        // 2) MMA phase on buffer `cur`
        const uint32_t sAhi = sb + (cur ? SM_A1HI : SM_A0HI);
        const uint32_t sAlo = sb + (cur ? SM_A1LO : SM_A0LO);
        const int nhi_off = cur ? SM_A0HI : SM_A1HI;
        const int nlo_off = cur ? SM_A0LO : SM_A1LO;

        float acc[2][8][4];
#pragma unroll
        for (int mt = 0; mt < 2; mt++)
#pragma unroll
            for (int nt = 0; nt < 8; nt++)
#pragma unroll
                for (int j = 0; j < 4; j++) acc[mt][nt][j] = 0.0f;

#pragma unroll
        for (int ks = 0; ks < 8; ks++) {
            const uint32_t kb = (uint32_t)ks * 32;

            // A fragments (hi/lo, both 16-row subtiles)
            uint32_t ahi[2][4], alo[2][4];
            ldmatrix_x4(ahi[0][0], ahi[0][1], ahi[0][2], ahi[0][3], sAhi + aoff0 + kb);
            ldmatrix_x4(ahi[1][0], ahi[1][1], ahi[1][2], ahi[1][3], sAhi + aoff1 + kb);
            ldmatrix_x4(alo[0][0], alo[0][1], alo[0][2], alo[0][3], sAlo + aoff0 + kb);
            ldmatrix_x4(alo[1][0], alo[1][1], alo[1][2], alo[1][3], sAlo + aoff1 + kb);

            // ALL B fragments for this warp's 64 columns, register-resident
            uint32_t bhi[4][4], blo[4][4];
#pragma unroll
            for (int np = 0; np < 4; np++) {
                const uint32_t nb = (uint32_t)(nw * 64 + np * 16) * PITCH;
                ldmatrix_x4(bhi[np][0], bhi[np][1], bhi[np][2], bhi[np][3],
                            sWhi + boff + nb + kb);
                ldmatrix_x4(blo[np][0], blo[np][1], blo[np][2], blo[np][3],
                            sWlo + boff + nb + kb);
            }

            // product 1: ahi * bhi  (16 independent accumulators in sequence)
#pragma unroll
            for (int np = 0; np < 4; np++)
#pragma unroll
                for (int j = 0; j < 2; j++)
#pragma unroll
                    for (int mt = 0; mt < 2; mt++)
                        mma_bf16(acc[mt][np * 2 + j], ahi[mt], &bhi[np][2 * j]);
            // product 2: ahi * blo
#pragma unroll
            for (int np = 0; np < 4; np++)
#pragma unroll
                for (int j = 0; j < 2; j++)
#pragma unroll
                    for (int mt = 0; mt < 2; mt++)
                        mma_bf16(acc[mt][np * 2 + j], ahi[mt], &blo[np][2 * j]);
            // product 3: alo * bhi
#pragma unroll
            for (int np = 0; np < 4; np++)
#pragma unroll
                for (int j = 0; j < 2; j++)
#pragma unroll
                    for (int mt = 0; mt < 2; mt++)
                        mma_bf16(acc[mt][np * 2 + j], alo[mt], &bhi[np][2 * j]);

            // drain staging registers mid-loop (dest buffer not read this iter)
            if (ks == 2 && have_next)
                cvt_sts_half(smem, nhi_off, nlo_off, tid, st, 0);
            if (ks == 5 && have_next)
                cvt_sts_half(smem, nhi_off, nlo_off, tid, st, 1);
        }

        // 3) epilogue: bias + STG for tile t
#pragma unroll
        for (int mt = 0; mt < 2; mt++) {
            const size_t rbase = (size_t)t * TILE_M + mw * 32 + mt * 16 + (l >> 2);
#pragma unroll
            for (int nt = 0; nt < 8; nt++) {
                const int col = nw * 64 + nt * 8 + cpair;
                float2 v0 = make_float2(acc[mt][nt][0] + bx[nt], acc[mt][nt][1] + by[nt]);
                float2 v1 = make_float2(acc[mt][nt][2] + bx[nt], acc[mt][nt][3] + by[nt]);
                *(float2*)(y + rbase * D + col)       = v0;
                *(float2*)(y + (rbase + 8) * D + col) = v1;
            }
        }

        __syncthreads();
        cur ^= 1;
    }
}

// ============================================================================

extern "C" void kernel_launch(void* const* d_in, const int* in_sizes, int n_in,
                              void* d_out, int out_size) {
    const float* x    = (const float*)d_in[0];  // [16, 8192, 128]
    const float* W    = (const float*)d_in[1];  // [4, 128, 128]
    const float* b    = (const float*)d_in[2];  // [4, 128]
    const float* wsel = (const float*)d_in[3];  // [4]
    float* y = (float*)d_out;                   // [16, 8192, 128]

    static bool attr_set = false;
    if (!attr_set) {
        cudaFuncSetAttribute(gemm_kernel,
                             cudaFuncAttributeMaxDynamicSharedMemorySize, SM_TOTAL);
        attr_set = true;
    }
    gemm_kernel<<<GRID, NTHR, SM_TOTAL>>>(x, W, b, wsel, y);
}

// round 6
// speedup vs baseline: 1.6878x; 1.0705x over previous
#include <cuda_runtime.h>
#include <cuda_bf16.h>
#include <cstdint>

// ============================================================================
// y = x @ W_eff^T + b_eff   (exact collapse of the one-hot op mixture)
// x: [131072, 128] fp32.  Warp-level mma.sync bf16, 3-term split
// (xhi*Whi + xhi*Wlo + xlo*Whi), fp32 accum.
// R6: 512 threads / 16 warps (4Mx4N warp grid, 32x32 warp tile). Halves
//     every per-thread register class (acc 32, staging 32, frags 32) so the
//     kernel stops spilling (R4/R5 were pinned at 255 regs -> 2 warps/SMSP
//     -> exposed LDS latency). 4 warps/SMSP doubles latency hiding.
// ============================================================================

static constexpr int D       = 128;
static constexpr int TILE_M  = 128;
static constexpr int N_ROWS  = 16 * 8192;            // 131072
static constexpr int N_TILES = N_ROWS / TILE_M;      // 1024
static constexpr int GRID    = 148;                  // persistent, 1 CTA/SM
static constexpr int NTHR    = 512;                  // 16 warps: 4M x 4N

// bf16 tiles: pitch 272 B keeps ldmatrix row addresses conflict-free.
static constexpr int PITCH   = 272;
static constexpr int WTILE   = 128 * PITCH;          // 34816 B
static constexpr int SM_WHI  = 0;
static constexpr int SM_WLO  = SM_WHI + WTILE;
static constexpr int SM_A0HI = SM_WLO + WTILE;
static constexpr int SM_A0LO = SM_A0HI + WTILE;
static constexpr int SM_A1HI = SM_A0LO + WTILE;
static constexpr int SM_A1LO = SM_A1HI + WTILE;
static constexpr int SM_TOTAL = SM_A1LO + WTILE;     // 208896 B

// ---------------- PTX helpers (baseline ISA only) ---------------------------

__device__ __forceinline__ uint32_t smem_to_u32(const void* p) {
    uint32_t a;
    asm("{ .reg .u64 t; cvta.to.shared.u64 t, %1; cvt.u32.u64 %0, t; }"
        : "=r"(a) : "l"(p));
    return a;
}

__device__ __forceinline__ void ldmatrix_x4(uint32_t& r0, uint32_t& r1,
                                            uint32_t& r2, uint32_t& r3,
                                            uint32_t addr) {
    asm volatile("ldmatrix.sync.aligned.m8n8.x4.shared.b16 {%0,%1,%2,%3}, [%4];"
                 : "=r"(r0), "=r"(r1), "=r"(r2), "=r"(r3) : "r"(addr));
}

__device__ __forceinline__ void mma_bf16(float* c, const uint32_t* a,
                                         const uint32_t* b) {
    asm volatile(
        "mma.sync.aligned.m16n8k16.row.col.f32.bf16.bf16.f32 "
        "{%0,%1,%2,%3}, {%4,%5,%6,%7}, {%8,%9}, {%0,%1,%2,%3};"
        : "+f"(c[0]), "+f"(c[1]), "+f"(c[2]), "+f"(c[3])
        : "r"(a[0]), "r"(a[1]), "r"(a[2]), "r"(a[3]), "r"(b[0]), "r"(b[1]));
}

__device__ __forceinline__ uint32_t pack_hi(float a, float b) {
    __nv_bfloat16 h0 = __float2bfloat16(a);
    __nv_bfloat16 h1 = __float2bfloat16(b);
    return (uint32_t)__bfloat16_as_ushort(h0) |
           ((uint32_t)__bfloat16_as_ushort(h1) << 16);
}
__device__ __forceinline__ uint32_t pack_lo(float a, float b) {
    __nv_bfloat16 h0 = __float2bfloat16(a);
    __nv_bfloat16 h1 = __float2bfloat16(b);
    __nv_bfloat16 l0 = __float2bfloat16(a - __bfloat162float(h0));
    __nv_bfloat16 l1 = __float2bfloat16(b - __bfloat162float(h1));
    return (uint32_t)__bfloat16_as_ushort(l0) |
           ((uint32_t)__bfloat16_as_ushort(l1) << 16);
}

// issue the 8 LDG.128 for one 128x128 fp32 tile (per-thread share, 512 thr)
__device__ __forceinline__ void ldg_tile(const float4* __restrict__ xg,
                                         int tid, float4* st) {
#pragma unroll
    for (int it = 0; it < 4; it++) {
        const int i  = tid + it * NTHR;      // 0..2047 chunk-pairs
        const int r  = i >> 4;
        const int c8 = i & 15;
        st[2 * it]     = xg[r * 32 + c8 * 2];
        st[2 * it + 1] = xg[r * 32 + c8 * 2 + 1];
    }
}

// convert HALF of the staged tile (it in [2h, 2h+2)) and store to SMEM
__device__ __forceinline__ void cvt_sts_half(char* smem_base, int hi_off, int lo_off,
                                             int tid, const float4* st, int h) {
#pragma unroll
    for (int it = 2 * h; it < 2 * h + 2; it++) {
        const int i  = tid + it * NTHR;
        const int r  = i >> 4;
        const int c8 = i & 15;
        const float4 v0 = st[2 * it];
        const float4 v1 = st[2 * it + 1];
        uint4 hip, lop;
        hip.x = pack_hi(v0.x, v0.y);  lop.x = pack_lo(v0.x, v0.y);
        hip.y = pack_hi(v0.z, v0.w);  lop.y = pack_lo(v0.z, v0.w);
        hip.z = pack_hi(v1.x, v1.y);  lop.z = pack_lo(v1.x, v1.y);
        hip.w = pack_hi(v1.z, v1.w);  lop.w = pack_lo(v1.z, v1.w);
        const int off = r * PITCH + c8 * 16;
        *(uint4*)(smem_base + hi_off + off) = hip;
        *(uint4*)(smem_base + lo_off + off) = lop;
    }
}

// ============================================================================
__global__ void __launch_bounds__(NTHR, 1)
gemm_kernel(const float* __restrict__ x,
            const float* __restrict__ W,
            const float* __restrict__ bias,
            const float* __restrict__ wsel,
            float* __restrict__ y) {
    extern __shared__ char smem[];
    const uint32_t sb  = smem_to_u32(smem);
    const int tid  = threadIdx.x;
    const int w    = tid >> 5;
    const int l    = tid & 31;
    const int mw   = w & 3;          // M quarter (rows mw*32 .. +31)
    const int nw4  = w >> 2;         // N quarter (cols nw4*32 .. +31)

    const float w0 = wsel[0], w1 = wsel[1], w2 = wsel[2], w3 = wsel[3];

    // ---- compute W_eff (bf16 hi/lo) directly into SMEM ----
#pragma unroll
    for (int j = 0; j < 32; j++) {                   // 16384 / 512
        const int idx = tid + j * NTHR;
        const float v = w0 * W[idx] + w1 * W[16384 + idx]
                      + w2 * W[32768 + idx] + w3 * W[49152 + idx];
        __nv_bfloat16 hi = __float2bfloat16(v);
        __nv_bfloat16 lo = __float2bfloat16(v - __bfloat162float(hi));
        const int f = idx >> 7, d = idx & 127;
        const int off = f * PITCH + d * 2;
        *(__nv_bfloat16*)(smem + SM_WHI + off) = hi;
        *(__nv_bfloat16*)(smem + SM_WLO + off) = lo;
    }

    // ---- per-lane bias values (constant across tiles) ----
    const int cpair = (l & 3) * 2;
    float bx[4], by[4];
#pragma unroll
    for (int nt = 0; nt < 4; nt++) {
        const int col = nw4 * 32 + nt * 8 + cpair;
        bx[nt] = w0 * bias[col]       + w1 * bias[128 + col]
               + w2 * bias[256 + col] + w3 * bias[384 + col];
        by[nt] = w0 * bias[col + 1]   + w1 * bias[129 + col]
               + w2 * bias[257 + col] + w3 * bias[385 + col];
    }

    // ---- prologue: load + convert + store tile t0 into buffer 0 ----
    int t = blockIdx.x;
    {
        float4 st[8];
        ldg_tile((const float4*)(x + (size_t)t * TILE_M * D), tid, st);
        cvt_sts_half(smem, SM_A0HI, SM_A0LO, tid, st, 0);
        cvt_sts_half(smem, SM_A0HI, SM_A0LO, tid, st, 1);
    }
    __syncthreads();

    // ldmatrix per-lane offsets
    const uint32_t aoff0 = (uint32_t)((mw * 32 +      (l & 15)) * PITCH + ((l >> 4) & 1) * 16);
    const uint32_t aoff1 = aoff0 + 16u * PITCH;
    const uint32_t boff  = (uint32_t)((((l >> 4) & 1) * 8 + (l & 7)) * PITCH
                                      + ((l >> 3) & 1) * 16);
    const uint32_t sWhi = sb + SM_WHI, sWlo = sb + SM_WLO;

    int cur = 0;
    for (; t < N_TILES; t += GRID) {
        const int tn = t + GRID;
        const bool have_next = tn < N_TILES;

        // 1) issue next tile's global loads (latency hides under MMAs)
        float4 st[8];
        if (have_next)
            ldg_tile((const float4*)(x + (size_t)tn * TILE_M * D), tid, st);

        // 2) MMA phase on buffer `cur`
        const uint32_t sAhi = sb + (cur ? SM_A1HI : SM_A0HI);
        const uint32_t sAlo = sb + (cur ? SM_A1LO : SM_A0LO);
        const int nhi_off = cur ? SM_A0HI : SM_A1HI;
        const int nlo_off = cur ? SM_A0LO : SM_A1LO;

        float acc[2][4][4];
#pragma unroll
        for (int mt = 0; mt < 2; mt++)
#pragma unroll
            for (int nt = 0; nt < 4; nt++)
#pragma unroll
                for (int j = 0; j < 4; j++) acc[mt][nt][j] = 0.0f;

#pragma unroll
        for (int ks = 0; ks < 8; ks++) {
            const uint32_t kb = (uint32_t)ks * 32;

            // A fragments (hi/lo, both 16-row subtiles)
            uint32_t ahi[2][4], alo[2][4];
            ldmatrix_x4(ahi[0][0], ahi[0][1], ahi[0][2], ahi[0][3], sAhi + aoff0 + kb);
            ldmatrix_x4(ahi[1][0], ahi[1][1], ahi[1][2], ahi[1][3], sAhi + aoff1 + kb);
            ldmatrix_x4(alo[0][0], alo[0][1], alo[0][2], alo[0][3], sAlo + aoff0 + kb);
            ldmatrix_x4(alo[1][0], alo[1][1], alo[1][2], alo[1][3], sAlo + aoff1 + kb);

            // B fragments for this warp's 32 columns (2 pairs, hi/lo)
            uint32_t bhi[2][4], blo[2][4];
#pragma unroll
            for (int np = 0; np < 2; np++) {
                const uint32_t nb = (uint32_t)(nw4 * 32 + np * 16) * PITCH;
                ldmatrix_x4(bhi[np][0], bhi[np][1], bhi[np][2], bhi[np][3],
                            sWhi + boff + nb + kb);
                ldmatrix_x4(blo[np][0], blo[np][1], blo[np][2], blo[np][3],
                            sWlo + boff + nb + kb);
            }

            // 24 MMAs grouped by product (8 independent accumulators each)
#pragma unroll
            for (int np = 0; np < 2; np++)
#pragma unroll
                for (int j = 0; j < 2; j++)
#pragma unroll
                    for (int mt = 0; mt < 2; mt++)
                        mma_bf16(acc[mt][np * 2 + j], ahi[mt], &bhi[np][2 * j]);
#pragma unroll
            for (int np = 0; np < 2; np++)
#pragma unroll
                for (int j = 0; j < 2; j++)
#pragma unroll
                    for (int mt = 0; mt < 2; mt++)
                        mma_bf16(acc[mt][np * 2 + j], ahi[mt], &blo[np][2 * j]);
#pragma unroll
            for (int np = 0; np < 2; np++)
#pragma unroll
                for (int j = 0; j < 2; j++)
#pragma unroll
                    for (int mt = 0; mt < 2; mt++)
                        mma_bf16(acc[mt][np * 2 + j], alo[mt], &bhi[np][2 * j]);

            // drain staging registers mid-loop (dest buffer not read this iter)
            if (ks == 2 && have_next)
                cvt_sts_half(smem, nhi_off, nlo_off, tid, st, 0);
            if (ks == 5 && have_next)
                cvt_sts_half(smem, nhi_off, nlo_off, tid, st, 1);
        }

        // 3) epilogue: bias + STG for tile t
#pragma unroll
        for (int mt = 0; mt < 2; mt++) {
            const size_t rbase = (size_t)t * TILE_M + mw * 32 + mt * 16 + (l >> 2);
#pragma unroll
            for (int nt = 0; nt < 4; nt++) {
                const int col = nw4 * 32 + nt * 8 + cpair;
                float2 v0 = make_float2(acc[mt][nt][0] + bx[nt], acc[mt][nt][1] + by[nt]);
                float2 v1 = make_float2(acc[mt][nt][2] + bx[nt], acc[mt][nt][3] + by[nt]);
                *(float2*)(y + rbase * D + col)       = v0;
                *(float2*)(y + (rbase + 8) * D + col) = v1;
            }
        }

        __syncthreads();
        cur ^= 1;
    }
}

// ============================================================================

extern "C" void kernel_launch(void* const* d_in, const int* in_sizes, int n_in,
                              void* d_out, int out_size) {
    const float* x    = (const float*)d_in[0];  // [16, 8192, 128]
    const float* W    = (const float*)d_in[1];  // [4, 128, 128]
    const float* b    = (const float*)d_in[2];  // [4, 128]
    const float* wsel = (const float*)d_in[3];  // [4]
    float* y = (float*)d_out;                   // [16, 8192, 128]

    static bool attr_set = false;
    if (!attr_set) {
        cudaFuncSetAttribute(gemm_kernel,
                             cudaFuncAttributeMaxDynamicSharedMemorySize, SM_TOTAL);
        attr_set = true;
    }
    gemm_kernel<<<GRID, NTHR, SM_TOTAL>>>(x, W, b, wsel, y);
}

// round 7
// speedup vs baseline: 1.9147x; 1.1344x over previous
#include <cuda_runtime.h>
#include <cuda_fp16.h>
#include <cstdint>

// ============================================================================
// y = x @ W_eff^T + b_eff   (exact collapse of the one-hot op mixture)
// x: [131072, 128] fp32.  R7: SINGLE fp16 product (no hi/lo split).
// Error model: per-input rounding 2^-11.5 -> global rel_err ~3-5e-4 < 1e-3
// (measured 4.5e-6 at effective 2^-18 confirms the scaling law).
// Cuts MMA work 3x, ldmatrix 2x, SMEM traffic 2x vs R6 -> DRAM-bound.
// ============================================================================

static constexpr int D       = 128;
static constexpr int TILE_M  = 128;
static constexpr int N_ROWS  = 16 * 8192;            // 131072
static constexpr int N_TILES = N_ROWS / TILE_M;      // 1024
static constexpr int GRID    = 148;                  // persistent, 1 CTA/SM
static constexpr int NTHR    = 512;                  // 16 warps: 4M x 4N

// fp16 tiles: pitch 272 B keeps ldmatrix row addresses conflict-free.
static constexpr int PITCH   = 272;
static constexpr int WTILE   = 128 * PITCH;          // 34816 B
static constexpr int SM_W    = 0;
static constexpr int SM_A0   = SM_W + WTILE;
static constexpr int SM_A1   = SM_A0 + WTILE;
static constexpr int SM_TOTAL = SM_A1 + WTILE;       // 104448 B

// ---------------- PTX helpers (baseline ISA only) ---------------------------

__device__ __forceinline__ uint32_t smem_to_u32(const void* p) {
    uint32_t a;
    asm("{ .reg .u64 t; cvta.to.shared.u64 t, %1; cvt.u32.u64 %0, t; }"
        : "=r"(a) : "l"(p));
    return a;
}

__device__ __forceinline__ void ldmatrix_x4(uint32_t& r0, uint32_t& r1,
                                            uint32_t& r2, uint32_t& r3,
                                            uint32_t addr) {
    asm volatile("ldmatrix.sync.aligned.m8n8.x4.shared.b16 {%0,%1,%2,%3}, [%4];"
                 : "=r"(r0), "=r"(r1), "=r"(r2), "=r"(r3) : "r"(addr));
}

__device__ __forceinline__ void mma_f16(float* c, const uint32_t* a,
                                        const uint32_t* b) {
    asm volatile(
        "mma.sync.aligned.m16n8k16.row.col.f32.f16.f16.f32 "
        "{%0,%1,%2,%3}, {%4,%5,%6,%7}, {%8,%9}, {%0,%1,%2,%3};"
        : "+f"(c[0]), "+f"(c[1]), "+f"(c[2]), "+f"(c[3])
        : "r"(a[0]), "r"(a[1]), "r"(a[2]), "r"(a[3]), "r"(b[0]), "r"(b[1]));
}

__device__ __forceinline__ uint32_t pack_h2(float a, float b) {
    __half2 h = __floats2half2_rn(a, b);
    return *(uint32_t*)&h;
}

// issue the 8 LDG.128 for one 128x128 fp32 tile (per-thread share, 512 thr)
__device__ __forceinline__ void ldg_tile(const float4* __restrict__ xg,
                                         int tid, float4* st) {
#pragma unroll
    for (int it = 0; it < 4; it++) {
        const int i  = tid + it * NTHR;      // 0..2047 chunk-pairs
        const int r  = i >> 4;
        const int c8 = i & 15;
        st[2 * it]     = xg[r * 32 + c8 * 2];
        st[2 * it + 1] = xg[r * 32 + c8 * 2 + 1];
    }
}

// convert HALF of the staged tile (it in [2h, 2h+2)) to fp16, store to SMEM
__device__ __forceinline__ void cvt_sts_half(char* smem_base, int a_off,
                                             int tid, const float4* st, int h) {
#pragma unroll
    for (int it = 2 * h; it < 2 * h + 2; it++) {
        const int i  = tid + it * NTHR;
        const int r  = i >> 4;
        const int c8 = i & 15;
        const float4 v0 = st[2 * it];
        const float4 v1 = st[2 * it + 1];
        uint4 hp;
        hp.x = pack_h2(v0.x, v0.y);
        hp.y = pack_h2(v0.z, v0.w);
        hp.z = pack_h2(v1.x, v1.y);
        hp.w = pack_h2(v1.z, v1.w);
        const int off = r * PITCH + c8 * 16;
        *(uint4*)(smem_base + a_off + off) = hp;
    }
}

// ============================================================================
__global__ void __launch_bounds__(NTHR, 1)
gemm_kernel(const float* __restrict__ x,
            const float* __restrict__ W,
            const float* __restrict__ bias,
            const float* __restrict__ wsel,
            float* __restrict__ y) {
    extern __shared__ char smem[];
    const uint32_t sb  = smem_to_u32(smem);
    const int tid  = threadIdx.x;
    const int w    = tid >> 5;
    const int l    = tid & 31;
    const int mw   = w & 3;          // M quarter (rows mw*32 .. +31)
    const int nw4  = w >> 2;         // N quarter (cols nw4*32 .. +31)

    const float w0 = wsel[0], w1 = wsel[1], w2 = wsel[2], w3 = wsel[3];

    // ---- compute W_eff (fp16) directly into SMEM ----
#pragma unroll
    for (int j = 0; j < 32; j++) {                   // 16384 / 512
        const int idx = tid + j * NTHR;
        const float v = w0 * W[idx] + w1 * W[16384 + idx]
                      + w2 * W[32768 + idx] + w3 * W[49152 + idx];
        const int f = idx >> 7, d = idx & 127;
        *(__half*)(smem + SM_W + f * PITCH + d * 2) = __float2half_rn(v);
    }

    // ---- per-lane bias values (constant across tiles) ----
    const int cpair = (l & 3) * 2;
    float bx[4], by[4];
#pragma unroll
    for (int nt = 0; nt < 4; nt++) {
        const int col = nw4 * 32 + nt * 8 + cpair;
        bx[nt] = w0 * bias[col]       + w1 * bias[128 + col]
               + w2 * bias[256 + col] + w3 * bias[384 + col];
        by[nt] = w0 * bias[col + 1]   + w1 * bias[129 + col]
               + w2 * bias[257 + col] + w3 * bias[385 + col];
    }

    // ---- prologue: load + convert + store tile t0 into buffer 0 ----
    int t = blockIdx.x;
    {
        float4 st[8];
        ldg_tile((const float4*)(x + (size_t)t * TILE_M * D), tid, st);
        cvt_sts_half(smem, SM_A0, tid, st, 0);
        cvt_sts_half(smem, SM_A0, tid, st, 1);
    }
    __syncthreads();

    // ldmatrix per-lane offsets
    const uint32_t aoff0 = (uint32_t)((mw * 32 +      (l & 15)) * PITCH + ((l >> 4) & 1) * 16);
    const uint32_t aoff1 = aoff0 + 16u * PITCH;
    const uint32_t boff  = (uint32_t)((((l >> 4) & 1) * 8 + (l & 7)) * PITCH
                                      + ((l >> 3) & 1) * 16);
    const uint32_t sW = sb + SM_W;

    int cur = 0;
    for (; t < N_TILES; t += GRID) {
        const int tn = t + GRID;
        const bool have_next = tn < N_TILES;

        // 1) issue next tile's global loads (latency hides under MMAs)
        float4 st[8];
        if (have_next)
            ldg_tile((const float4*)(x + (size_t)tn * TILE_M * D), tid, st);

        // 2) MMA phase on buffer `cur`
        const uint32_t sA = sb + (cur ? SM_A1 : SM_A0);
        const int n_off   = cur ? SM_A0 : SM_A1;

        float acc[2][4][4];
#pragma unroll
        for (int mt = 0; mt < 2; mt++)
#pragma unroll
            for (int nt = 0; nt < 4; nt++)
#pragma unroll
                for (int j = 0; j < 4; j++) acc[mt][nt][j] = 0.0f;

#pragma unroll
        for (int ks = 0; ks < 8; ks++) {
            const uint32_t kb = (uint32_t)ks * 32;

            // A fragments (both 16-row subtiles)
            uint32_t a0[2][4];
            ldmatrix_x4(a0[0][0], a0[0][1], a0[0][2], a0[0][3], sA + aoff0 + kb);
            ldmatrix_x4(a0[1][0], a0[1][1], a0[1][2], a0[1][3], sA + aoff1 + kb);

            // B fragments for this warp's 32 columns (2 n-tile pairs)
            uint32_t bf[2][4];
#pragma unroll
            for (int np = 0; np < 2; np++) {
                const uint32_t nb = (uint32_t)(nw4 * 32 + np * 16) * PITCH;
                ldmatrix_x4(bf[np][0], bf[np][1], bf[np][2], bf[np][3],
                            sW + boff + nb + kb);
            }

            // 8 MMAs, 8 independent accumulators
#pragma unroll
            for (int np = 0; np < 2; np++)
#pragma unroll
                for (int j = 0; j < 2; j++)
#pragma unroll
                    for (int mt = 0; mt < 2; mt++)
                        mma_f16(acc[mt][np * 2 + j], a0[mt], &bf[np][2 * j]);

            // drain staging registers mid-loop (dest buffer not read this iter)
            if (ks == 2 && have_next)
                cvt_sts_half(smem, n_off, tid, st, 0);
            if (ks == 5 && have_next)
                cvt_sts_half(smem, n_off, tid, st, 1);
        }

        // 3) epilogue: bias + STG for tile t
#pragma unroll
        for (int mt = 0; mt < 2; mt++) {
            const size_t rbase = (size_t)t * TILE_M + mw * 32 + mt * 16 + (l >> 2);
#pragma unroll
            for (int nt = 0; nt < 4; nt++) {
                const int col = nw4 * 32 + nt * 8 + cpair;
                float2 v0 = make_float2(acc[mt][nt][0] + bx[nt], acc[mt][nt][1] + by[nt]);
                float2 v1 = make_float2(acc[mt][nt][2] + bx[nt], acc[mt][nt][3] + by[nt]);
                *(float2*)(y + rbase * D + col)       = v0;
                *(float2*)(y + (rbase + 8) * D + col) = v1;
            }
        }

        __syncthreads();
        cur ^= 1;
    }
}

// ============================================================================

extern "C" void kernel_launch(void* const* d_in, const int* in_sizes, int n_in,
                              void* d_out, int out_size) {
    const float* x    = (const float*)d_in[0];  // [16, 8192, 128]
    const float* W    = (const float*)d_in[1];  // [4, 128, 128]
    const float* b    = (const float*)d_in[2];  // [4, 128]
    const float* wsel = (const float*)d_in[3];  // [4]
    float* y = (float*)d_out;                   // [16, 8192, 128]

    static bool attr_set = false;
    if (!attr_set) {
        cudaFuncSetAttribute(gemm_kernel,
                             cudaFuncAttributeMaxDynamicSharedMemorySize, SM_TOTAL);
        attr_set = true;
    }
    gemm_kernel<<<GRID, NTHR, SM_TOTAL>>>(x, W, b, wsel, y);
}

// round 9
// speedup vs baseline: 2.0949x; 1.0941x over previous
#include <cuda_runtime.h>
#include <cuda_fp16.h>
#include <cstdint>

// ============================================================================
// y = x @ W_eff^T + b_eff   (exact collapse of the one-hot op mixture)
// x: [131072, 128] fp32.  Single fp16 product (rel_err ~2.9e-4 measured).
// R9 = R8 with the issue_tile indexing bug fixed (fp32 rows are 512B = 32
//     chunks of 16B: r = i>>5, c = i&31; R8 used >>3/&7 -> OOB cp.async).
// cp.async 2-stage fp32 A ring; A fragments via LDS.64 + F2FP pack per
// k-step; W fp16 via ldmatrix; persistent 148-CTA grid.
// ============================================================================

static constexpr int D       = 128;
static constexpr int TILE_M  = 128;
static constexpr int N_TILES = 1024;
static constexpr int GRID    = 148;                  // persistent, 1 CTA/SM
static constexpr int NTHR    = 512;                  // 16 warps: 4M x 4N

static constexpr int PITCHW  = 272;                  // fp16 W tile pitch
static constexpr int WTILE   = 128 * PITCHW;         // 34816 B
static constexpr int PITCHX  = 528;                  // fp32 x tile pitch
static constexpr int XTILE   = 128 * PITCHX;         // 67584 B
static constexpr int SM_W    = 0;
static constexpr int SM_X0   = WTILE;
static constexpr int SM_X1   = WTILE + XTILE;
static constexpr int SM_TOTAL = WTILE + 2 * XTILE;   // 169984 B

// ---------------- PTX helpers (baseline ISA only) ---------------------------

__device__ __forceinline__ uint32_t smem_to_u32(const void* p) {
    uint32_t a;
    asm("{ .reg .u64 t; cvta.to.shared.u64 t, %1; cvt.u32.u64 %0, t; }"
        : "=r"(a) : "l"(p));
    return a;
}

__device__ __forceinline__ void ldmatrix_x4(uint32_t& r0, uint32_t& r1,
                                            uint32_t& r2, uint32_t& r3,
                                            uint32_t addr) {
    asm volatile("ldmatrix.sync.aligned.m8n8.x4.shared.b16 {%0,%1,%2,%3}, [%4];"
                 : "=r"(r0), "=r"(r1), "=r"(r2), "=r"(r3) : "r"(addr));
}

__device__ __forceinline__ void mma_f16(float* c, const uint32_t* a,
                                        const uint32_t* b) {
    asm volatile(
        "mma.sync.aligned.m16n8k16.row.col.f32.f16.f16.f32 "
        "{%0,%1,%2,%3}, {%4,%5,%6,%7}, {%8,%9}, {%0,%1,%2,%3};"
        : "+f"(c[0]), "+f"(c[1]), "+f"(c[2]), "+f"(c[3])
        : "r"(a[0]), "r"(a[1]), "r"(a[2]), "r"(a[3]), "r"(b[0]), "r"(b[1]));
}

__device__ __forceinline__ uint32_t pack_h2(float a, float b) {
    __half2 h = __floats2half2_rn(a, b);
    return *(uint32_t*)&h;
}

__device__ __forceinline__ void cp_async16(uint32_t saddr, const void* g) {
    asm volatile("cp.async.cg.shared.global [%0], [%1], 16;"
                 :: "r"(saddr), "l"(g) : "memory");
}
#define CP_COMMIT() asm volatile("cp.async.commit_group;" ::: "memory")
#define CP_WAIT1()  asm volatile("cp.async.wait_group 1;" ::: "memory")

// issue the 4096 cp.async (16B each) for one 128x128 fp32 tile.
// Rows are 512 B = 32 chunks of 16 B: r = i>>5 (0..127), c16 = i&31.
__device__ __forceinline__ void issue_tile(uint32_t sx, const float* xg, int tid) {
#pragma unroll
    for (int it = 0; it < 8; it++) {
        const int i   = tid + it * NTHR;     // 0..4095
        const int r   = i >> 5;              // row 0..127
        const int c16 = i & 31;              // 16B chunk within 512B row
        cp_async16(sx + (uint32_t)(r * PITCHX + c16 * 16),
                   (const char*)xg + r * 512 + c16 * 16);
    }
}

// ============================================================================
__global__ void __launch_bounds__(NTHR, 1)
gemm_kernel(const float* __restrict__ x,
            const float* __restrict__ W,
            const float* __restrict__ bias,
            const float* __restrict__ wsel,
            float* __restrict__ y) {
    extern __shared__ char smem[];
    const uint32_t sb  = smem_to_u32(smem);
    const int tid  = threadIdx.x;
    const int w    = tid >> 5;
    const int l    = tid & 31;
    const int mw   = w & 3;          // M quarter (rows mw*32 .. +31)
    const int nw4  = w >> 2;         // N quarter (cols nw4*32 .. +31)

    const float w0 = wsel[0], w1 = wsel[1], w2 = wsel[2], w3 = wsel[3];

    // ---- compute W_eff (fp16) directly into SMEM ----
#pragma unroll
    for (int j = 0; j < 32; j++) {                   // 16384 / 512
        const int idx = tid + j * NTHR;
        const float v = w0 * W[idx] + w1 * W[16384 + idx]
                      + w2 * W[32768 + idx] + w3 * W[49152 + idx];
        const int f = idx >> 7, d = idx & 127;
        *(__half*)(smem + SM_W + f * PITCHW + d * 2) = __float2half_rn(v);
    }

    // ---- per-lane bias values (constant across tiles) ----
    const int cpair = (l & 3) * 2;
    float bx[4], by[4];
#pragma unroll
    for (int nt = 0; nt < 4; nt++) {
        const int col = nw4 * 32 + nt * 8 + cpair;
        bx[nt] = w0 * bias[col]       + w1 * bias[128 + col]
               + w2 * bias[256 + col] + w3 * bias[384 + col];
        by[nt] = w0 * bias[col + 1]   + w1 * bias[129 + col]
               + w2 * bias[257 + col] + w3 * bias[385 + col];
    }

    // ---- prologue: prefetch tiles t and t+GRID ----
    int t = blockIdx.x;
    issue_tile(sb + SM_X0, x + (size_t)t * TILE_M * D, tid);
    CP_COMMIT();
    if (t + GRID < N_TILES)
        issue_tile(sb + SM_X1, x + (size_t)(t + GRID) * TILE_M * D, tid);
    CP_COMMIT();

    // per-lane A base (bytes within an x stage): row = mw*32 + l/4, col pair (l&3)*2
    const uint32_t abase = (uint32_t)((mw * 32 + (l >> 2)) * PITCHX + (l & 3) * 8);
    // B ldmatrix per-lane offset
    const uint32_t boff  = (uint32_t)((((l >> 4) & 1) * 8 + (l & 7)) * PITCHW
                                      + ((l >> 3) & 1) * 16);
    const uint32_t sW = sb + SM_W;

    int s = 0;
    for (; t < N_TILES; t += GRID) {
        CP_WAIT1();                    // stage s complete (prefetched 1 tile ago)
        __syncthreads();

        const int xoff = s ? SM_X1 : SM_X0;

        float acc[2][4][4];
#pragma unroll
        for (int mt = 0; mt < 2; mt++)
#pragma unroll
            for (int nt = 0; nt < 4; nt++)
#pragma unroll
                for (int j = 0; j < 4; j++) acc[mt][nt][j] = 0.0f;

#pragma unroll
        for (int ks = 0; ks < 8; ks++) {
            const uint32_t kbX = (uint32_t)ks * 64;   // 16 floats
            const uint32_t kbW = (uint32_t)ks * 32;   // 16 halves

            // A fragments from fp32 SMEM: 4 LDS.64 + 4 packs per m-subtile
            uint32_t a[2][4];
#pragma unroll
            for (int mt = 0; mt < 2; mt++) {
                const char* ab = smem + xoff + abase + mt * (16 * PITCHX) + kbX;
                const float2 p0 = *(const float2*)(ab);                    // (r,  k0)
                const float2 p1 = *(const float2*)(ab + 8 * PITCHX);       // (r+8,k0)
                const float2 p2 = *(const float2*)(ab + 32);               // (r,  k8)
                const float2 p3 = *(const float2*)(ab + 8 * PITCHX + 32);  // (r+8,k8)
                a[mt][0] = pack_h2(p0.x, p0.y);
                a[mt][1] = pack_h2(p1.x, p1.y);
                a[mt][2] = pack_h2(p2.x, p2.y);
                a[mt][3] = pack_h2(p3.x, p3.y);
            }

            // B fragments (W fp16, ldmatrix)
            uint32_t bf[2][4];
#pragma unroll
            for (int np = 0; np < 2; np++) {
                const uint32_t nb = (uint32_t)(nw4 * 32 + np * 16) * PITCHW;
                ldmatrix_x4(bf[np][0], bf[np][1], bf[np][2], bf[np][3],
                            sW + boff + nb + kbW);
            }

            // 8 MMAs, 8 independent accumulators
#pragma unroll
            for (int np = 0; np < 2; np++)
#pragma unroll
                for (int j = 0; j < 2; j++)
#pragma unroll
                    for (int mt = 0; mt < 2; mt++)
                        mma_f16(acc[mt][np * 2 + j], a[mt], &bf[np][2 * j]);
        }

        // epilogue: bias + STG for tile t
#pragma unroll
        for (int mt = 0; mt < 2; mt++) {
            const size_t rbase = (size_t)t * TILE_M + mw * 32 + mt * 16 + (l >> 2);
#pragma unroll
            for (int nt = 0; nt < 4; nt++) {
                const int col = nw4 * 32 + nt * 8 + cpair;
                float2 v0 = make_float2(acc[mt][nt][0] + bx[nt], acc[mt][nt][1] + by[nt]);
                float2 v1 = make_float2(acc[mt][nt][2] + bx[nt], acc[mt][nt][3] + by[nt]);
                *(float2*)(y + rbase * D + col)       = v0;
                *(float2*)(y + (rbase + 8) * D + col) = v1;
            }
        }

        __syncthreads();               // all warps done reading stage s

        // prefetch t+2*GRID into the stage just freed (always commit a group
        // so the wait_group(1) bookkeeping stays uniform)
        if (t + 2 * GRID < N_TILES)
            issue_tile(sb + (uint32_t)xoff,
                       x + (size_t)(t + 2 * GRID) * TILE_M * D, tid);
        CP_COMMIT();

        s ^= 1;
    }
}

// ============================================================================

extern "C" void kernel_launch(void* const* d_in, const int* in_sizes, int n_in,
                              void* d_out, int out_size) {
    const float* x    = (const float*)d_in[0];  // [16, 8192, 128]
    const float* W    = (const float*)d_in[1];  // [4, 128, 128]
    const float* b    = (const float*)d_in[2];  // [4, 128]
    const float* wsel = (const float*)d_in[3];  // [4]
    float* y = (float*)d_out;                   // [16, 8192, 128]

    static bool attr_set = false;
    if (!attr_set) {
        cudaFuncSetAttribute(gemm_kernel,
                             cudaFuncAttributeMaxDynamicSharedMemorySize, SM_TOTAL);
        attr_set = true;
    }
    gemm_kernel<<<GRID, NTHR, SM_TOTAL>>>(x, W, b, wsel, y);
}

// round 10
// speedup vs baseline: 2.4413x; 1.1654x over previous
#include <cuda_runtime.h>
#include <cuda_fp16.h>
#include <cstdint>

// ============================================================================
// y = x @ W_eff^T + b_eff   (exact collapse of the one-hot op mixture)
// x: [131072, 128] fp32.  Single fp16 product (rel_err ~2.9e-4).
// R10: A fragments loaded DIRECTLY from global x (no SMEM staging, no
//      cp.async, no barriers in the main loop). Warp tile 16x128: 8 warps
//      own disjoint row ranges -> every x element read exactly once, by the
//      thread that feeds it to the MMA. W fp16 in SMEM (ldmatrix), bias in
//      registers. Free-running warps; DRAM becomes the binding pipe.
// ============================================================================

static constexpr int D       = 128;
static constexpr int TILE_M  = 128;
static constexpr int N_TILES = 1024;
static constexpr int GRID    = 148;                  // persistent, 1 CTA/SM
static constexpr int NTHR    = 256;                  // 8 warps x 16 rows = 128

static constexpr int PITCHW  = 272;                  // fp16 W tile pitch
static constexpr int WTILE   = 128 * PITCHW;         // 34816 B
static constexpr int SM_W    = 0;
static constexpr int SM_BIAS = WTILE;                // 512 B
static constexpr int SM_TOTAL = WTILE + 512;

// ---------------- PTX helpers (baseline ISA only) ---------------------------

__device__ __forceinline__ uint32_t smem_to_u32(const void* p) {
    uint32_t a;
    asm("{ .reg .u64 t; cvta.to.shared.u64 t, %1; cvt.u32.u64 %0, t; }"
        : "=r"(a) : "l"(p));
    return a;
}

__device__ __forceinline__ void ldmatrix_x4(uint32_t& r0, uint32_t& r1,
                                            uint32_t& r2, uint32_t& r3,
                                            uint32_t addr) {
    asm volatile("ldmatrix.sync.aligned.m8n8.x4.shared.b16 {%0,%1,%2,%3}, [%4];"
                 : "=r"(r0), "=r"(r1), "=r"(r2), "=r"(r3) : "r"(addr));
}

__device__ __forceinline__ void mma_f16(float* c, const uint32_t* a,
                                        const uint32_t* b) {
    asm volatile(
        "mma.sync.aligned.m16n8k16.row.col.f32.f16.f16.f32 "
        "{%0,%1,%2,%3}, {%4,%5,%6,%7}, {%8,%9}, {%0,%1,%2,%3};"
        : "+f"(c[0]), "+f"(c[1]), "+f"(c[2]), "+f"(c[3])
        : "r"(a[0]), "r"(a[1]), "r"(a[2]), "r"(a[3]), "r"(b[0]), "r"(b[1]));
}

__device__ __forceinline__ uint32_t pack_h2(float a, float b) {
    __half2 h = __floats2half2_rn(a, b);
    return *(uint32_t*)&h;
}

// ============================================================================
__global__ void __launch_bounds__(NTHR, 1)
gemm_kernel(const float* __restrict__ x,
            const float* __restrict__ W,
            const float* __restrict__ bias,
            const float* __restrict__ wsel,
            float* __restrict__ y) {
    extern __shared__ char smem[];
    const uint32_t sb  = smem_to_u32(smem);
    const int tid  = threadIdx.x;
    const int w    = tid >> 5;       // warp 0..7 -> rows w*16 .. w*16+15
    const int l    = tid & 31;

    const float w0 = wsel[0], w1 = wsel[1], w2 = wsel[2], w3 = wsel[3];

    // ---- stage W_eff (fp16) into SMEM ----
#pragma unroll
    for (int j = 0; j < 64; j++) {                   // 16384 / 256
        const int idx = tid + j * NTHR;
        const float v = w0 * W[idx] + w1 * W[16384 + idx]
                      + w2 * W[32768 + idx] + w3 * W[49152 + idx];
        const int f = idx >> 7, d = idx & 127;
        *(__half*)(smem + SM_W + f * PITCHW + d * 2) = __float2half_rn(v);
    }
    if (tid < 128) {
        ((float*)(smem + SM_BIAS))[tid] =
            w0 * bias[tid] + w1 * bias[128 + tid]
          + w2 * bias[256 + tid] + w3 * bias[384 + tid];
    }
    __syncthreads();                 // the ONLY block-wide barrier

    // ---- per-lane bias registers (16 col pairs) ----
    const int cpair = (l & 3) * 2;
    float bx[16], by[16];
#pragma unroll
    for (int nt = 0; nt < 16; nt++) {
        const int col = nt * 8 + cpair;
        bx[nt] = ((const float*)(smem + SM_BIAS))[col];
        by[nt] = ((const float*)(smem + SM_BIAS))[col + 1];
    }

    // B ldmatrix per-lane offset: lanes 0-7 nt k-lo, 8-15 nt k-hi,
    //                             16-23 nt+1 k-lo, 24-31 nt+1 k-hi
    const uint32_t boff = (uint32_t)((((l >> 4) & 1) * 8 + (l & 7)) * PITCHW
                                     + ((l >> 3) & 1) * 16);
    const uint32_t sW = sb + SM_W;

    // per-thread A row pointer: row = t*128 + w*16 + l/4, col (l&3)*2
    const int rbase_in_tile = w * 16 + (l >> 2);

    for (int t = blockIdx.x; t < N_TILES; t += GRID) {
        const float* xr = x + ((size_t)t * TILE_M + rbase_in_tile) * D + cpair;

        float acc[16][4];
#pragma unroll
        for (int nt = 0; nt < 16; nt++)
#pragma unroll
            for (int j = 0; j < 4; j++) acc[nt][j] = 0.0f;

#pragma unroll
        for (int ks = 0; ks < 8; ks++) {
            // A fragment directly from global (exact m16n8k16 layout)
            const float2 plo0 = *(const float2*)(xr + ks * 16);            // (r,   k0k1)
            const float2 phi0 = *(const float2*)(xr + 8 * D + ks * 16);    // (r+8, k0k1)
            const float2 plo8 = *(const float2*)(xr + ks * 16 + 8);        // (r,   k8k9)
            const float2 phi8 = *(const float2*)(xr + 8 * D + ks * 16 + 8);// (r+8, k8k9)
            uint32_t a[4];
            a[0] = pack_h2(plo0.x, plo0.y);
            a[1] = pack_h2(phi0.x, phi0.y);
            a[2] = pack_h2(plo8.x, plo8.y);
            a[3] = pack_h2(phi8.x, phi8.y);

            // B fragments: 8 x4-ldmatrix cover all 16 n-tiles
            uint32_t bq[8][4];
#pragma unroll
            for (int np = 0; np < 8; np++) {
                const uint32_t nb = (uint32_t)(np * 16) * PITCHW;
                ldmatrix_x4(bq[np][0], bq[np][1], bq[np][2], bq[np][3],
                            sW + boff + nb + (uint32_t)ks * 32);
            }

            // 16 MMAs into 16 independent accumulators
#pragma unroll
            for (int np = 0; np < 8; np++) {
                mma_f16(acc[np * 2 + 0], a, &bq[np][0]);
                mma_f16(acc[np * 2 + 1], a, &bq[np][2]);
            }
        }

        // epilogue: bias + STG
        const size_t row = (size_t)t * TILE_M + rbase_in_tile;
#pragma unroll
        for (int nt = 0; nt < 16; nt++) {
            const int col = nt * 8 + cpair;
            float2 v0 = make_float2(acc[nt][0] + bx[nt], acc[nt][1] + by[nt]);
            float2 v1 = make_float2(acc[nt][2] + bx[nt], acc[nt][3] + by[nt]);
            *(float2*)(y + row * D + col)       = v0;
            *(float2*)(y + (row + 8) * D + col) = v1;
        }
    }
}

// ============================================================================

extern "C" void kernel_launch(void* const* d_in, const int* in_sizes, int n_in,
                              void* d_out, int out_size) {
    const float* x    = (const float*)d_in[0];  // [16, 8192, 128]
    const float* W    = (const float*)d_in[1];  // [4, 128, 128]
    const float* b    = (const float*)d_in[2];  // [4, 128]
    const float* wsel = (const float*)d_in[3];  // [4]
    float* y = (float*)d_out;                   // [16, 8192, 128]

    static bool attr_set = false;
    if (!attr_set) {
        cudaFuncSetAttribute(gemm_kernel,
                             cudaFuncAttributeMaxDynamicSharedMemorySize, SM_TOTAL);
        attr_set = true;
    }
    gemm_kernel<<<GRID, NTHR, SM_TOTAL>>>(x, W, b, wsel, y);
}

// round 11
// speedup vs baseline: 2.7211x; 1.1146x over previous
#include <cuda_runtime.h>
#include <cuda_fp16.h>
#include <cstdint>

// ============================================================================
// y = x @ W_eff^T + b_eff   (exact collapse of the one-hot op mixture)
// x: [131072, 128] fp32.  Single fp16 product (rel_err ~2.9e-4).
// R11: A loads as 2x LDG.128 (float4) per k-step instead of 4x LDG.64, made
//      legal by permuting k WITHIN each 16-k block identically on A and B:
//      fragment-k (2j+m) <- data-k (4j+m), (2j+8+m) <- (4j+2+m). The
//      permutation is baked into the W SMEM staging (one-time); A's float4
//      then maps to the fragment with plain packs. Halves A wavefronts and
//      LSU issues. Everything else as R10 (no main-loop barriers).
// ============================================================================

static constexpr int D       = 128;
static constexpr int TILE_M  = 128;
static constexpr int N_TILES = 1024;
static constexpr int GRID    = 148;                  // persistent, 1 CTA/SM
static constexpr int NTHR    = 256;                  // 8 warps x 16 rows

static constexpr int PITCHW  = 272;                  // fp16 W tile pitch
static constexpr int WTILE   = 128 * PITCHW;         // 34816 B
static constexpr int SM_W    = 0;
static constexpr int SM_BIAS = WTILE;                // 512 B
static constexpr int SM_TOTAL = WTILE + 512;

// ---------------- PTX helpers (baseline ISA only) ---------------------------

__device__ __forceinline__ uint32_t smem_to_u32(const void* p) {
    uint32_t a;
    asm("{ .reg .u64 t; cvta.to.shared.u64 t, %1; cvt.u32.u64 %0, t; }"
        : "=r"(a) : "l"(p));
    return a;
}

__device__ __forceinline__ void ldmatrix_x4(uint32_t& r0, uint32_t& r1,
                                            uint32_t& r2, uint32_t& r3,
                                            uint32_t addr) {
    asm volatile("ldmatrix.sync.aligned.m8n8.x4.shared.b16 {%0,%1,%2,%3}, [%4];"
                 : "=r"(r0), "=r"(r1), "=r"(r2), "=r"(r3) : "r"(addr));
}

__device__ __forceinline__ void mma_f16(float* c, const uint32_t* a,
                                        const uint32_t* b) {
    asm volatile(
        "mma.sync.aligned.m16n8k16.row.col.f32.f16.f16.f32 "
        "{%0,%1,%2,%3}, {%4,%5,%6,%7}, {%8,%9}, {%0,%1,%2,%3};"
        : "+f"(c[0]), "+f"(c[1]), "+f"(c[2]), "+f"(c[3])
        : "r"(a[0]), "r"(a[1]), "r"(a[2]), "r"(a[3]), "r"(b[0]), "r"(b[1]));
}

__device__ __forceinline__ uint32_t pack_h2(float a, float b) {
    __half2 h = __floats2half2_rn(a, b);
    return *(uint32_t*)&h;
}

// ============================================================================
__global__ void __launch_bounds__(NTHR, 1)
gemm_kernel(const float* __restrict__ x,
            const float* __restrict__ W,
            const float* __restrict__ bias,
            const float* __restrict__ wsel,
            float* __restrict__ y) {
    extern __shared__ char smem[];
    const uint32_t sb  = smem_to_u32(smem);
    const int tid  = threadIdx.x;
    const int w    = tid >> 5;       // warp 0..7 -> rows w*16 .. w*16+15
    const int l    = tid & 31;

    const float w0 = wsel[0], w1 = wsel[1], w2 = wsel[2], w3 = wsel[3];

    // ---- stage W_eff (fp16) into SMEM with per-16-block k-permutation ----
    // fragment-k (2j+m) holds data-k (4j+m); (2j+8+m) holds (4j+2+m).
    // For global data col d: j=(d&15)>>2, m=d&3; fk = 2j+m (+6 if m>=2).
#pragma unroll
    for (int jj = 0; jj < 64; jj++) {                // 16384 / 256
        const int idx = tid + jj * NTHR;
        const float v = w0 * W[idx] + w1 * W[16384 + idx]
                      + w2 * W[32768 + idx] + w3 * W[49152 + idx];
        const int f  = idx >> 7, d = idx & 127;
        const int b  = d >> 4, dk = d & 15;
        const int j  = dk >> 2, m = dk & 3;
        const int fk = 2 * j + m + ((m >= 2) ? 6 : 0);
        const int col = b * 16 + fk;
        *(__half*)(smem + SM_W + f * PITCHW + col * 2) = __float2half_rn(v);
    }
    if (tid < 128) {
        ((float*)(smem + SM_BIAS))[tid] =
            w0 * bias[tid] + w1 * bias[128 + tid]
          + w2 * bias[256 + tid] + w3 * bias[384 + tid];
    }
    __syncthreads();                 // the ONLY block-wide barrier

    // ---- per-lane bias registers (16 col pairs) ----
    const int cpair = (l & 3) * 2;
    float bx[16], by[16];
#pragma unroll
    for (int nt = 0; nt < 16; nt++) {
        const int col = nt * 8 + cpair;
        bx[nt] = ((const float*)(smem + SM_BIAS))[col];
        by[nt] = ((const float*)(smem + SM_BIAS))[col + 1];
    }

    // B ldmatrix per-lane offset (unchanged; permutation handled in staging)
    const uint32_t boff = (uint32_t)((((l >> 4) & 1) * 8 + (l & 7)) * PITCHW
                                     + ((l >> 3) & 1) * 16);
    const uint32_t sW = sb + SM_W;

    // per-thread A row/col: row = t*128 + w*16 + l/4, col floats (l&3)*4
    const int rbase_in_tile = w * 16 + (l >> 2);
    const int acol = (l & 3) * 4;

    for (int t = blockIdx.x; t < N_TILES; t += GRID) {
        const float* xr = x + ((size_t)t * TILE_M + rbase_in_tile) * D + acol;

        float acc[16][4];
#pragma unroll
        for (int nt = 0; nt < 16; nt++)
#pragma unroll
            for (int j = 0; j < 4; j++) acc[nt][j] = 0.0f;

#pragma unroll
        for (int ks = 0; ks < 8; ks++) {
            // A fragment: 2x LDG.128 (consecutive k), permuted mapping
            const float4 lo = *(const float4*)(xr + ks * 16);          // row r
            const float4 hi = *(const float4*)(xr + 8 * D + ks * 16);  // row r+8
            uint32_t a[4];
            a[0] = pack_h2(lo.x, lo.y);   // (r,   fk 2j,2j+1) = data 4j,4j+1
            a[1] = pack_h2(hi.x, hi.y);   // (r+8, fk 2j,2j+1)
            a[2] = pack_h2(lo.z, lo.w);   // (r,   fk 2j+8,2j+9) = data 4j+2,4j+3
            a[3] = pack_h2(hi.z, hi.w);   // (r+8, fk 2j+8,2j+9)

            // B fragments: 8 x4-ldmatrix cover all 16 n-tiles
            uint32_t bq[8][4];
#pragma unroll
            for (int np = 0; np < 8; np++) {
                const uint32_t nb = (uint32_t)(np * 16) * PITCHW;
                ldmatrix_x4(bq[np][0], bq[np][1], bq[np][2], bq[np][3],
                            sW + boff + nb + (uint32_t)ks * 32);
            }

            // 16 MMAs into 16 independent accumulators
#pragma unroll
            for (int np = 0; np < 8; np++) {
                mma_f16(acc[np * 2 + 0], a, &bq[np][0]);
                mma_f16(acc[np * 2 + 1], a, &bq[np][2]);
            }
        }

        // epilogue: bias + STG
        const size_t row = (size_t)t * TILE_M + rbase_in_tile;
#pragma unroll
        for (int nt = 0; nt < 16; nt++) {
            const int col = nt * 8 + cpair;
            float2 v0 = make_float2(acc[nt][0] + bx[nt], acc[nt][1] + by[nt]);
            float2 v1 = make_float2(acc[nt][2] + bx[nt], acc[nt][3] + by[nt]);
            *(float2*)(y + row * D + col)       = v0;
            *(float2*)(y + (row + 8) * D + col) = v1;
        }
    }
}

// ============================================================================

extern "C" void kernel_launch(void* const* d_in, const int* in_sizes, int n_in,
                              void* d_out, int out_size) {
    const float* x    = (const float*)d_in[0];  // [16, 8192, 128]
    const float* W    = (const float*)d_in[1];  // [4, 128, 128]
    const float* b    = (const float*)d_in[2];  // [4, 128]
    const float* wsel = (const float*)d_in[3];  // [4]
    float* y = (float*)d_out;                   // [16, 8192, 128]

    static bool attr_set = false;
    if (!attr_set) {
        cudaFuncSetAttribute(gemm_kernel,
                             cudaFuncAttributeMaxDynamicSharedMemorySize, SM_TOTAL);
        attr_set = true;
    }
    gemm_kernel<<<GRID, NTHR, SM_TOTAL>>>(x, W, b, wsel, y);
}